// round 2
// baseline (speedup 1.0000x reference)
#include <cuda_runtime.h>
#include <math.h>

// ---------------- problem constants ----------------
#define BATCH 128
#define C1 256          // conv1 out channels
#define H1 20           // conv1 out spatial
#define C2 256          // conv2 out channels
#define H2 12           // conv2 out spatial
#define NMAP 32
#define NPRIM 144       // 12*12
#define NCAP (NMAP*NPRIM)   // 4608
#define NCLS 10
#define OD 16
#define ID 8

#define OUT_OHE_OFF 0
#define OUT_REC_OFF (BATCH*NCLS)                    // 1280
#define OUT_LEN_OFF (BATCH*NCLS + BATCH*784)        // 101632

// ---------------- device scratch ----------------
__device__ float g_conv1[(size_t)BATCH*C1*H1*H1];            // 13.1M f
__device__ float g_p[(size_t)BATCH*C2*H2*H2];                // 4.7M f
__device__ float g_u[(size_t)BATCH*NCAP*ID];                 // 4.7M f
__device__ float g_v[BATCH*NCLS*OD];
__device__ float g_vc[BATCH*NCLS*OD];                        // cumulative v (== b_ij generator)
__device__ int   g_cls[BATCH];
__device__ float g_h1[BATCH*512];
__device__ float g_h2[BATCH*1024];

// ---------------- packed f32x2 helpers ----------------
__device__ __forceinline__ void pack2(unsigned long long& d, float lo, float hi) {
    asm("mov.b64 %0, {%1, %2};" : "=l"(d) : "f"(lo), "f"(hi));
}
__device__ __forceinline__ void unpack2(float& lo, float& hi, unsigned long long d) {
    asm("mov.b64 {%0, %1}, %2;" : "=f"(lo), "=f"(hi) : "l"(d));
}
__device__ __forceinline__ void ffma2(unsigned long long& acc, unsigned long long a,
                                      unsigned long long b) {
    asm("fma.rn.f32x2 %0, %1, %2, %0;" : "+l"(acc) : "l"(a), "l"(b));
}

// ---------------- conv1 + relu ----------------
__global__ __launch_bounds__(256) void conv1_kernel(
    const float* __restrict__ img, const float* __restrict__ w,
    const float* __restrict__ bias)
{
    int oc = blockIdx.x, b = blockIdx.y;
    __shared__ float si[28*28];
    __shared__ float sw[81];
    int t = threadIdx.x;
    for (int i = t; i < 784; i += 256) si[i] = img[b*784 + i];
    if (t < 81) sw[t] = w[oc*81 + t];
    __syncthreads();
    float bs = bias[oc];
    for (int pos = t; pos < 400; pos += 256) {
        int oy = pos / 20, ox = pos % 20;
        float a = 0.f;
        #pragma unroll
        for (int ky = 0; ky < 9; ky++) {
            #pragma unroll
            for (int kx = 0; kx < 9; kx++)
                a = fmaf(sw[ky*9+kx], si[(oy+ky)*28 + ox + kx], a);
        }
        a += bs;
        g_conv1[(((size_t)b*C1 + oc)*H1 + oy)*H1 + ox] = fmaxf(a, 0.f);
    }
}

// ---------------- conv2 with FFMA2 (f32x2) ----------------
// block = (32-oc tile, b); 192 threads: thread = (oc-pair 0..15, oy 0..11)
// each thread computes 2 oc x 12 ox with packed fma.rn.f32x2
#define ICB 4
#define OCB 32
__global__ __launch_bounds__(192) void conv2_kernel(
    const float* __restrict__ w2, const float* __restrict__ b2)
{
    int octile = blockIdx.x;            // 0..7
    int b = blockIdx.y;
    int t = threadIdx.x;                // 0..191
    int pr = t / 12;                    // oc-pair index 0..15
    int oy = t % 12;

    __shared__ float xs[ICB][400];              // 6.4 KB
    __shared__ float wsf[ICB*81*OCB];           // 41.5 KB, [(ic*81+k)*32 + oc_l]

    unsigned long long acc[12];
    #pragma unroll
    for (int i = 0; i < 12; i++) acc[i] = 0ull; // bits of (0.f,0.f)

    const float* xin = g_conv1 + (size_t)b*C1*400;

    for (int ic0 = 0; ic0 < C1; ic0 += ICB) {
        __syncthreads();
        for (int i = t; i < ICB*400; i += 192) {
            int ic = i / 400, r = i % 400;
            xs[ic][r] = xin[(size_t)(ic0 + ic)*400 + r];
        }
        // weights: k fastest across lanes (coalesced), stored oc-interleaved
        for (int i = t; i < OCB*ICB*81; i += 192) {
            int oc_l = i / (ICB*81);
            int r = i % (ICB*81);
            int ic = r / 81, k = r % 81;
            wsf[(ic*81 + k)*OCB + oc_l] =
                w2[((size_t)(octile*OCB + oc_l)*C1 + ic0 + ic)*81 + k];
        }
        __syncthreads();

        #pragma unroll 1
        for (int ic = 0; ic < ICB; ic++) {
            #pragma unroll 1
            for (int ky = 0; ky < 9; ky++) {
                unsigned long long xx[20];
                #pragma unroll
                for (int i = 0; i < 20; i++) {
                    float xv = xs[ic][(oy+ky)*20 + i];
                    pack2(xx[i], xv, xv);
                }
                const float* wrow = &wsf[(ic*81 + ky*9)*OCB + 2*pr];
                #pragma unroll
                for (int kx = 0; kx < 9; kx++) {
                    unsigned long long wp =
                        *(const unsigned long long*)&wrow[kx*OCB];
                    #pragma unroll
                    for (int ox = 0; ox < 12; ox++)
                        ffma2(acc[ox], wp, xx[ox + kx]);
                }
            }
        }
    }

    int oc0 = octile*OCB + 2*pr;
    float bv0 = b2[oc0], bv1 = b2[oc0+1];
    #pragma unroll
    for (int ox = 0; ox < 12; ox++) {
        float lo, hi;
        unpack2(lo, hi, acc[ox]);
        g_p[(((size_t)b*C2 + oc0)*H2 + oy)*H2 + ox]     = lo + bv0;
        g_p[(((size_t)b*C2 + oc0 + 1)*H2 + oy)*H2 + ox] = hi + bv1;
    }
}

// ---------------- primary capsule squash ----------------
__global__ void squash_prim_kernel()
{
    int idx = blockIdx.x*blockDim.x + threadIdx.x;
    if (idx >= BATCH*NCAP) return;
    int pos = idx % NPRIM;
    int m   = (idx / NPRIM) % NMAP;
    int b   = idx / NCAP;
    float x[ID]; float s2 = 0.f;
    #pragma unroll
    for (int d = 0; d < ID; d++) {
        x[d] = g_p[(((size_t)b*C2 + d*NMAP + m)*NPRIM) + pos];
        s2 = fmaf(x[d], x[d], s2);
    }
    float scale = (s2 / (1.f + s2)) / sqrtf(s2 + 1e-8f);
    float* up = g_u + (size_t)idx*ID;
    #pragma unroll
    for (int d = 0; d < ID; d++) up[d] = scale * x[d];
}

// ---------------- fused routing ----------------
// b_ij at iter i == dot(u_hat[n,c], Vc[c]) with Vc = sum of previous v's.
// softmax normalization is a scalar divide: s_j = (sum e*uh) / (sum e).
// So each iteration is a single pass recomputing u_hat from W (L2-resident).
__global__ void vc_zero_kernel()
{
    int idx = blockIdx.x*256 + threadIdx.x;
    if (idx < BATCH*NCLS*OD) g_vc[idx] = 0.f;
}

__global__ __launch_bounds__(512) void route_fused_kernel(
    const float* __restrict__ Wd, int last)
{
    int c = blockIdx.x, b = blockIdx.y;
    int t = threadIdx.x;
    __shared__ float sVc[16];
    __shared__ float sred[16][18];

    if (t < 16) sVc[t] = g_vc[(b*NCLS + c)*OD + t];
    __syncthreads();
    float Vc[16];
    #pragma unroll
    for (int o = 0; o < 16; o++) Vc[o] = sVc[o];

    float se = 0.f;
    float sv[16];
    #pragma unroll
    for (int o = 0; o < 16; o++) sv[o] = 0.f;

    #pragma unroll 1
    for (int j = 0; j < 9; j++) {
        int n = t + j*512;
        const float4* u4 = (const float4*)&g_u[((size_t)b*NCAP + n)*ID];
        float4 ua = u4[0], ub = u4[1];
        const float4* wp = (const float4*)&Wd[((size_t)n*NCLS + c)*OD*ID];
        float uh[16];
        float bcur = 0.f;
        #pragma unroll
        for (int o = 0; o < 16; o++) {
            float4 w0 = wp[2*o], w1 = wp[2*o+1];
            float a = w0.x*ua.x;
            a = fmaf(w0.y, ua.y, a); a = fmaf(w0.z, ua.z, a);
            a = fmaf(w0.w, ua.w, a); a = fmaf(w1.x, ub.x, a);
            a = fmaf(w1.y, ub.y, a); a = fmaf(w1.z, ub.z, a);
            a = fmaf(w1.w, ub.w, a);
            uh[o] = a;
            bcur = fmaf(a, Vc[o], bcur);
        }
        float e = __expf(bcur);
        se += e;
        #pragma unroll
        for (int o = 0; o < 16; o++) sv[o] = fmaf(e, uh[o], sv[o]);
    }

    // warp reduce 17 values
    #pragma unroll
    for (int off = 16; off > 0; off >>= 1) {
        se += __shfl_down_sync(0xffffffffu, se, off);
        #pragma unroll
        for (int o = 0; o < 16; o++)
            sv[o] += __shfl_down_sync(0xffffffffu, sv[o], off);
    }
    int wid = t >> 5, lane = t & 31;
    if (lane == 0) {
        sred[wid][0] = se;
        #pragma unroll
        for (int o = 0; o < 16; o++) sred[wid][1+o] = sv[o];
    }
    __syncthreads();

    if (t < 32) {
        float tot = 0.f;
        if (t < 17) {
            #pragma unroll
            for (int w = 0; w < 16; w++) tot += sred[w][t];
        }
        float setot = __shfl_sync(0xffffffffu, tot, 0);
        float s = (t >= 1 && t < 17) ? (tot / setot) : 0.f;
        float s2 = s*s;
        #pragma unroll
        for (int off = 16; off > 0; off >>= 1)
            s2 += __shfl_xor_sync(0xffffffffu, s2, off);
        float scale = (s2 / (1.f + s2)) / sqrtf(s2 + 1e-8f);
        if (t >= 1 && t < 17) {
            float vv = scale * s;
            int o = t - 1;
            g_v[(b*NCLS + c)*OD + o] = vv;
            if (!last) g_vc[(b*NCLS + c)*OD + o] += vv;
        }
    }
}

// ---------------- head ----------------
__global__ void head_kernel(float* __restrict__ out)
{
    int b = blockIdx.x;
    int t = threadIdx.x;   // 32
    __shared__ float len[NCLS];
    if (t < NCLS) {
        float s = 0.f;
        #pragma unroll
        for (int o = 0; o < OD; o++) {
            float x = g_v[(b*NCLS + t)*OD + o];
            s = fmaf(x, x, s);
        }
        len[t] = sqrtf(s);
    }
    __syncthreads();
    if (t == 0) {
        int best = 0; float bv = len[0];
        #pragma unroll
        for (int c = 1; c < NCLS; c++)
            if (len[c] > bv) { bv = len[c]; best = c; }
        g_cls[b] = best;
    }
    __syncthreads();
    int best = g_cls[b];
    if (t < NCLS) {
        out[OUT_OHE_OFF + b*NCLS + t] = (t == best) ? 1.0f : 0.0f;
        out[OUT_LEN_OFF + b*NCLS + t] = len[t];
    }
}

// ---------------- decoder ----------------
__global__ void dec1_kernel(const float* __restrict__ w1, const float* __restrict__ b1)
{
    int idx = blockIdx.x*256 + threadIdx.x;       // BATCH*512
    if (idx >= BATCH*512) return;
    int j = idx % 512, b = idx / 512;
    int cls = g_cls[b];
    const float* v = &g_v[(b*NCLS + cls)*OD];
    float a = b1[j];
    #pragma unroll
    for (int d = 0; d < OD; d++)
        a = fmaf(v[d], w1[(size_t)(cls*OD + d)*512 + j], a);
    g_h1[idx] = fmaxf(a, 0.f);
}

__global__ void dec2_kernel(const float* __restrict__ w2, const float* __restrict__ b2)
{
    int idx = blockIdx.x*256 + threadIdx.x;       // BATCH*1024
    if (idx >= BATCH*1024) return;
    int j = idx % 1024, b = idx / 1024;
    const float* h = &g_h1[b*512];
    float a = b2[j];
    #pragma unroll 4
    for (int k = 0; k < 512; k++)
        a = fmaf(h[k], w2[(size_t)k*1024 + j], a);
    g_h2[idx] = fmaxf(a, 0.f);
}

__global__ void dec3_kernel(const float* __restrict__ w3, const float* __restrict__ b3,
                            float* __restrict__ out)
{
    int idx = blockIdx.x*256 + threadIdx.x;       // BATCH*784
    if (idx >= BATCH*784) return;
    int p = idx % 784, b = idx / 784;
    const float* h = &g_h2[b*1024];
    float a = b3[p];
    #pragma unroll 4
    for (int k = 0; k < 1024; k++)
        a = fmaf(h[k], w3[(size_t)k*784 + p], a);
    out[OUT_REC_OFF + idx] = 1.f / (1.f + expf(-a));
}

// ---------------- launch ----------------
extern "C" void kernel_launch(void* const* d_in, const int* in_sizes, int n_in,
                              void* d_out, int out_size)
{
    const float* imgs    = (const float*)d_in[0];
    const float* conv1_w = (const float*)d_in[1];
    const float* conv1_b = (const float*)d_in[2];
    const float* conv2_w = (const float*)d_in[3];
    const float* conv2_b = (const float*)d_in[4];
    const float* W_digit = (const float*)d_in[5];
    const float* dec_w1  = (const float*)d_in[6];
    const float* dec_b1  = (const float*)d_in[7];
    const float* dec_w2  = (const float*)d_in[8];
    const float* dec_b2  = (const float*)d_in[9];
    const float* dec_w3  = (const float*)d_in[10];
    const float* dec_b3  = (const float*)d_in[11];
    float* out = (float*)d_out;

    conv1_kernel<<<dim3(C1, BATCH), 256>>>(imgs, conv1_w, conv1_b);
    conv2_kernel<<<dim3(C2/OCB, BATCH), 192>>>(conv2_w, conv2_b);
    {
        int n = BATCH*NCAP;
        squash_prim_kernel<<<(n + 255)/256, 256>>>();
    }
    vc_zero_kernel<<<(BATCH*NCLS*OD + 255)/256, 256>>>();
    for (int it = 0; it < 3; it++) {
        route_fused_kernel<<<dim3(NCLS, BATCH), 512>>>(W_digit, it == 2 ? 1 : 0);
    }
    head_kernel<<<BATCH, 32>>>(out);
    dec1_kernel<<<(BATCH*512 + 255)/256, 256>>>(dec_w1, dec_b1);
    dec2_kernel<<<(BATCH*1024 + 255)/256, 256>>>(dec_w2, dec_b2);
    dec3_kernel<<<(BATCH*784 + 255)/256, 256>>>(dec_w3, dec_b3, out);
    (void)in_sizes; (void)n_in; (void)out_size;
}

// round 4
// speedup vs baseline: 1.5450x; 1.5450x over previous
#include <cuda_runtime.h>
#include <cuda_bf16.h>
#include <math.h>
#include <stdint.h>

// ---------------- problem constants ----------------
#define BATCH 128
#define C1 256
#define H1 20
#define C2 256
#define H2 12
#define NMAP 32
#define NPRIM 144
#define NCAP (NMAP*NPRIM)   // 4608
#define NCLS 10
#define OD 16
#define ID 8

#define OUT_OHE_OFF 0
#define OUT_REC_OFF (BATCH*NCLS)
#define OUT_LEN_OFF (BATCH*NCLS + BATCH*784)

// conv2 GEMM geometry
#define KTOT 20736          // 256*81
#define KC   64             // K per chunk
#define NBLK 324            // 20736/64
#define MTILES 144          // 18432/128

// ---------------- device scratch ----------------
__device__ float g_conv1[(size_t)BATCH*C1*H1*H1];
__device__ float g_p[(size_t)BATCH*C2*H2*H2];
__device__ float g_u[(size_t)BATCH*NCAP*ID];
__device__ float g_v[BATCH*NCLS*OD];
__device__ float g_vc[BATCH*NCLS*OD];
__device__ int   g_cls[BATCH];
__device__ float g_h1[BATCH*512];
__device__ float g_h2[BATCH*1024];
__device__ __nv_bfloat16 g_wth[(size_t)KTOT*C2];   // W^T hi plane [k][oc]
__device__ __nv_bfloat16 g_wtl[(size_t)KTOT*C2];   // W^T lo plane
__device__ int g_xoff[KTOT];                       // im2col offset table

// ---------------- small PTX helpers ----------------
__device__ __forceinline__ uint32_t smem_u32(const void* p) {
    uint32_t a;
    asm("{ .reg .u64 t; cvta.to.shared.u64 t, %1; cvt.u32.u64 %0, t; }"
        : "=r"(a) : "l"(p));
    return a;
}
__device__ __forceinline__ void ldsm4(uint32_t* r, uint32_t a) {
    asm volatile("ldmatrix.sync.aligned.m8n8.x4.shared.b16 {%0,%1,%2,%3}, [%4];"
        : "=r"(r[0]), "=r"(r[1]), "=r"(r[2]), "=r"(r[3]) : "r"(a));
}
__device__ __forceinline__ void ldsm4t(uint32_t* r, uint32_t a) {
    asm volatile("ldmatrix.sync.aligned.m8n8.x4.trans.shared.b16 {%0,%1,%2,%3}, [%4];"
        : "=r"(r[0]), "=r"(r[1]), "=r"(r[2]), "=r"(r[3]) : "r"(a));
}
__device__ __forceinline__ void mma_bf16(float* c, const uint32_t* a, const uint32_t* b) {
    asm volatile("mma.sync.aligned.m16n8k16.row.col.f32.bf16.bf16.f32 "
        "{%0,%1,%2,%3}, {%4,%5,%6,%7}, {%8,%9}, {%0,%1,%2,%3};"
        : "+f"(c[0]), "+f"(c[1]), "+f"(c[2]), "+f"(c[3])
        : "r"(a[0]), "r"(a[1]), "r"(a[2]), "r"(a[3]), "r"(b[0]), "r"(b[1]));
}
__device__ __forceinline__ void cp16(uint32_t dst, const void* src) {
    asm volatile("cp.async.ca.shared.global [%0], [%1], 16;"
                 :: "r"(dst), "l"(src) : "memory");
}
__device__ __forceinline__ void cp_commit() {
    asm volatile("cp.async.commit_group;" ::: "memory");
}
__device__ __forceinline__ void cp_wait0() {
    asm volatile("cp.async.wait_group 0;" ::: "memory");
}
// bf16 hi/lo split of two floats into packed bf16x2 regs
__device__ __forceinline__ void split2(float x0, float x1, uint32_t& hp, uint32_t& lp) {
    asm("cvt.rn.bf16x2.f32 %0, %1, %2;" : "=r"(hp) : "f"(x1), "f"(x0));
    float h0 = __uint_as_float(hp << 16);
    float h1 = __uint_as_float(hp & 0xFFFF0000u);
    asm("cvt.rn.bf16x2.f32 %0, %1, %2;" : "=r"(lp) : "f"(x1 - h1), "f"(x0 - h0));
}
static __device__ __forceinline__ uint32_t sw128(uint32_t off) {
    return off ^ ((off >> 3) & 0x70);
}

// smem layout inside each buffer
#define OFF_XH 0u
#define OFF_XL 16384u
#define OFF_WH 32768u
#define OFF_WL 65536u
#define BUF_BYTES 98304u
#define CONV2_SMEM (2u*BUF_BYTES)   // 196608 bytes

// ---------------- one-time prep kernels ----------------
__global__ void xoff_kernel()
{
    int q = blockIdx.x*256 + threadIdx.x;
    if (q >= KTOT) return;
    int ic = q / 81;
    int r  = q - ic*81;
    int ky = r / 9;
    int kx = r - ky*9;
    g_xoff[q] = ic*400 + ky*20 + kx;
}

// w2[oc][k] -> Wt_h/Wt_l [k][oc]  (tiled transpose + split)
__global__ __launch_bounds__(256) void wsplit_kernel(const float* __restrict__ w2)
{
    __shared__ float s[32][33];
    int kt = blockIdx.x;     // 648
    int ot = blockIdx.y;     // 8
    int tx = threadIdx.x & 31;
    int ty = threadIdx.x >> 5;   // 0..7
    #pragma unroll
    for (int j = 0; j < 4; j++) {
        int oc = ot*32 + ty + j*8;
        s[ty + j*8][tx] = w2[(size_t)oc*KTOT + kt*32 + tx];
    }
    __syncthreads();
    #pragma unroll
    for (int j = 0; j < 4; j++) {
        int k  = kt*32 + ty + j*8;
        int oc = ot*32 + tx;
        float v = s[tx][ty + j*8];
        __nv_bfloat16 h = __float2bfloat16(v);
        float hv = __bfloat162float(h);
        g_wth[(size_t)k*C2 + oc] = h;
        g_wtl[(size_t)k*C2 + oc] = __float2bfloat16(v - hv);
    }
}

// ---------------- conv2 tensor-core kernel (mma.sync bf16 3-term) ----------------
__global__ void __launch_bounds__(256, 1) conv2_tc_kernel(const float* __restrict__ b2)
{
    extern __shared__ char smem[];
    uint32_t sbase = smem_u32(smem);
    int t = threadIdx.x;
    int warp = t >> 5, lane = t & 31;
    int tile = blockIdx.x;

    int warp_m = warp >> 2;        // 0..1  (64 pos each)
    int warp_n = warp & 3;         // 0..3  (64 oc each)

    // X staging mapping: thread -> (pos, k-half)
    int spos  = t >> 1;            // 0..127
    int khalf = (t & 1) * 32;
    int grow = tile*128 + spos;
    int bimg = grow / NPRIM;
    int posl = grow - bimg*NPRIM;
    int oy = posl / 12, ox = posl - (posl/12)*12;
    const float* actbase = g_conv1 + ((size_t)bimg*C1)*400 + oy*20 + ox;

    float acc[4][8][4];
    #pragma unroll
    for (int mt = 0; mt < 4; mt++)
        #pragma unroll
        for (int nt = 0; nt < 8; nt++)
            #pragma unroll
            for (int e = 0; e < 4; e++) acc[mt][nt][e] = 0.f;

    // ---- staging helpers (inline) ----
    // W: cp.async 16 chunks of 16B per thread per chunk
    // thread t handles idx = t*16 + i ; plane = idx/2048; rem=idx%2048; krow=rem/32; c16=rem%32
    // X: 32 f32 gathered -> split -> 4+4 uint4 STS

    // prologue: stage chunk 0 into buf0
    {
        // W cp.async
        #pragma unroll
        for (int i = 0; i < 16; i++) {
            int idx = t*16 + i;
            int plane = idx >> 11;
            int rem = idx & 2047;
            int krow = rem >> 5;
            int c16 = rem & 31;
            uint32_t dst = sbase + (plane ? OFF_WL : OFF_WH)
                         + krow*512u + (uint32_t)((c16*16) ^ ((krow & 7) << 4));
            const __nv_bfloat16* src = (plane ? g_wtl : g_wth)
                         + (size_t)(0*KC + krow)*C2 + c16*8;
            cp16(dst, src);
        }
        cp_commit();
        // X gather
        float xv[32];
        #pragma unroll
        for (int g = 0; g < 8; g++) {
            int4 off4 = *(const int4*)&g_xoff[0*KC + khalf + g*4];
            xv[g*4+0] = actbase[off4.x];
            xv[g*4+1] = actbase[off4.y];
            xv[g*4+2] = actbase[off4.z];
            xv[g*4+3] = actbase[off4.w];
        }
        uint32_t hp[16], lp[16];
        #pragma unroll
        for (int e = 0; e < 16; e++) split2(xv[2*e], xv[2*e+1], hp[e], lp[e]);
        #pragma unroll
        for (int c = 0; c < 4; c++) {
            uint32_t boff = sw128((uint32_t)(spos*128 + khalf*2 + c*16));
            *(uint4*)(smem + OFF_XH + boff) = make_uint4(hp[c*4], hp[c*4+1], hp[c*4+2], hp[c*4+3]);
            *(uint4*)(smem + OFF_XL + boff) = make_uint4(lp[c*4], lp[c*4+1], lp[c*4+2], lp[c*4+3]);
        }
        cp_wait0();
    }
    __syncthreads();

    for (int kb = 0; kb < NBLK; kb++) {
        uint32_t cur = (uint32_t)(kb & 1) * BUF_BYTES;
        uint32_t nxt = BUF_BYTES - cur;
        bool have_next = (kb + 1 < NBLK);

        float xv[32];
        if (have_next) {
            // issue W cp.async for kb+1
            #pragma unroll
            for (int i = 0; i < 16; i++) {
                int idx = t*16 + i;
                int plane = idx >> 11;
                int rem = idx & 2047;
                int krow = rem >> 5;
                int c16 = rem & 31;
                uint32_t dst = sbase + nxt + (plane ? OFF_WL : OFF_WH)
                             + krow*512u + (uint32_t)((c16*16) ^ ((krow & 7) << 4));
                const __nv_bfloat16* src = (plane ? g_wtl : g_wth)
                             + (size_t)((kb+1)*KC + krow)*C2 + c16*8;
                cp16(dst, src);
            }
            cp_commit();
            // issue X gather loads for kb+1
            #pragma unroll
            for (int g = 0; g < 8; g++) {
                int4 off4 = *(const int4*)&g_xoff[(kb+1)*KC + khalf + g*4];
                xv[g*4+0] = actbase[off4.x];
                xv[g*4+1] = actbase[off4.y];
                xv[g*4+2] = actbase[off4.z];
                xv[g*4+3] = actbase[off4.w];
            }
        }

        // ---- compute chunk kb from buf cur ----
        #pragma unroll
        for (int kk = 0; kk < 4; kk++) {
            uint32_t bh[8][2], bl[8][2];
            #pragma unroll
            for (int np = 0; np < 4; np++) {
                // B addr: j = lane>>3, rw = lane&7
                int j = lane >> 3, rw = lane & 7;
                int krow = kk*16 + (j & 1)*8 + rw;
                int ncol = warp_n*64 + np*16 + (j >> 1)*8;
                uint32_t byte = (uint32_t)(krow*512 + ((ncol*2) ^ ((krow & 7) << 4)));
                uint32_t r[4];
                ldsm4t(r, sbase + cur + OFF_WH + byte);
                bh[2*np][0] = r[0]; bh[2*np][1] = r[1];
                bh[2*np+1][0] = r[2]; bh[2*np+1][1] = r[3];
                ldsm4t(r, sbase + cur + OFF_WL + byte);
                bl[2*np][0] = r[0]; bl[2*np][1] = r[1];
                bl[2*np+1][0] = r[2]; bl[2*np+1][1] = r[3];
            }
            #pragma unroll
            for (int mt = 0; mt < 4; mt++) {
                int rowl = warp_m*64 + mt*16 + (lane & 15);
                uint32_t abyte = sw128((uint32_t)(rowl*128 + (kk*16 + (lane >> 4)*8)*2));
                uint32_t ah[4], al[4];
                ldsm4(ah, sbase + cur + OFF_XH + abyte);
                ldsm4(al, sbase + cur + OFF_XL + abyte);
                #pragma unroll
                for (int nt = 0; nt < 8; nt++) {
                    mma_bf16(acc[mt][nt], ah, bh[nt]);
                    mma_bf16(acc[mt][nt], ah, bl[nt]);
                    mma_bf16(acc[mt][nt], al, bh[nt]);
                }
            }
        }

        if (have_next) {
            // split + store X into nxt
            uint32_t hp[16], lp[16];
            #pragma unroll
            for (int e = 0; e < 16; e++) split2(xv[2*e], xv[2*e+1], hp[e], lp[e]);
            #pragma unroll
            for (int c = 0; c < 4; c++) {
                uint32_t boff = sw128((uint32_t)(spos*128 + khalf*2 + c*16));
                *(uint4*)(smem + nxt + OFF_XH + boff) = make_uint4(hp[c*4], hp[c*4+1], hp[c*4+2], hp[c*4+3]);
                *(uint4*)(smem + nxt + OFF_XL + boff) = make_uint4(lp[c*4], lp[c*4+1], lp[c*4+2], lp[c*4+3]);
            }
            cp_wait0();
        }
        __syncthreads();
    }

    // ---- epilogue: write D + bias to g_p ----
    #pragma unroll
    for (int mt = 0; mt < 4; mt++) {
        int pr0 = tile*128 + warp_m*64 + mt*16 + (lane >> 2);
        #pragma unroll
        for (int half = 0; half < 2; half++) {
            int pr = pr0 + half*8;
            int b = pr / NPRIM;
            int pl = pr - b*NPRIM;
            #pragma unroll
            for (int nt = 0; nt < 8; nt++) {
                int oc = warp_n*64 + nt*8 + (lane & 3)*2;
                float c0 = acc[mt][nt][half*2 + 0];
                float c1 = acc[mt][nt][half*2 + 1];
                g_p[((size_t)b*C2 + oc)*NPRIM + pl]     = c0 + __ldg(&b2[oc]);
                g_p[((size_t)b*C2 + oc + 1)*NPRIM + pl] = c1 + __ldg(&b2[oc+1]);
            }
        }
    }
}

// ---------------- conv1 + relu ----------------
__global__ __launch_bounds__(256) void conv1_kernel(
    const float* __restrict__ img, const float* __restrict__ w,
    const float* __restrict__ bias)
{
    int oc = blockIdx.x, b = blockIdx.y;
    __shared__ float si[28*28];
    __shared__ float sw[81];
    int t = threadIdx.x;
    for (int i = t; i < 784; i += 256) si[i] = img[b*784 + i];
    if (t < 81) sw[t] = w[oc*81 + t];
    __syncthreads();
    float bs = bias[oc];
    for (int p = t; p < 400; p += 256) {
        int oy = p / 20, ox = p % 20;
        float a = 0.f;
        #pragma unroll
        for (int ky = 0; ky < 9; ky++)
            #pragma unroll
            for (int kx = 0; kx < 9; kx++)
                a = fmaf(sw[ky*9+kx], si[(oy+ky)*28 + ox + kx], a);
        a += bs;
        g_conv1[(((size_t)b*C1 + oc)*H1 + oy)*H1 + ox] = fmaxf(a, 0.f);
    }
}

// ---------------- primary capsule squash ----------------
__global__ void squash_prim_kernel()
{
    int idx = blockIdx.x*blockDim.x + threadIdx.x;
    if (idx >= BATCH*NCAP) return;
    int pos = idx % NPRIM;
    int m   = (idx / NPRIM) % NMAP;
    int b   = idx / NCAP;
    float x[ID]; float s2 = 0.f;
    #pragma unroll
    for (int d = 0; d < ID; d++) {
        x[d] = g_p[(((size_t)b*C2 + d*NMAP + m)*NPRIM) + pos];
        s2 = fmaf(x[d], x[d], s2);
    }
    float scale = (s2 / (1.f + s2)) / sqrtf(s2 + 1e-8f);
    float* up = g_u + (size_t)idx*ID;
    #pragma unroll
    for (int d = 0; d < ID; d++) up[d] = scale * x[d];
}

// ---------------- fused routing ----------------
__global__ void vc_zero_kernel()
{
    int idx = blockIdx.x*256 + threadIdx.x;
    if (idx < BATCH*NCLS*OD) g_vc[idx] = 0.f;
}

__global__ __launch_bounds__(512) void route_fused_kernel(
    const float* __restrict__ Wd, int last)
{
    int c = blockIdx.x, b = blockIdx.y;
    int t = threadIdx.x;
    __shared__ float sVc[16];
    __shared__ float sred[16][18];

    if (t < 16) sVc[t] = g_vc[(b*NCLS + c)*OD + t];
    __syncthreads();
    float Vc[16];
    #pragma unroll
    for (int o = 0; o < 16; o++) Vc[o] = sVc[o];

    float se = 0.f;
    float sv[16];
    #pragma unroll
    for (int o = 0; o < 16; o++) sv[o] = 0.f;

    #pragma unroll 1
    for (int j = 0; j < 9; j++) {
        int n = t + j*512;
        const float4* u4 = (const float4*)&g_u[((size_t)b*NCAP + n)*ID];
        float4 ua = u4[0], ub = u4[1];
        const float4* wp = (const float4*)&Wd[((size_t)n*NCLS + c)*OD*ID];
        float uh[16];
        float bcur = 0.f;
        #pragma unroll
        for (int o = 0; o < 16; o++) {
            float4 w0 = wp[2*o], w1 = wp[2*o+1];
            float a = w0.x*ua.x;
            a = fmaf(w0.y, ua.y, a); a = fmaf(w0.z, ua.z, a);
            a = fmaf(w0.w, ua.w, a); a = fmaf(w1.x, ub.x, a);
            a = fmaf(w1.y, ub.y, a); a = fmaf(w1.z, ub.z, a);
            a = fmaf(w1.w, ub.w, a);
            uh[o] = a;
            bcur = fmaf(a, Vc[o], bcur);
        }
        float e = __expf(bcur);
        se += e;
        #pragma unroll
        for (int o = 0; o < 16; o++) sv[o] = fmaf(e, uh[o], sv[o]);
    }

    #pragma unroll
    for (int off = 16; off > 0; off >>= 1) {
        se += __shfl_down_sync(0xffffffffu, se, off);
        #pragma unroll
        for (int o = 0; o < 16; o++)
            sv[o] += __shfl_down_sync(0xffffffffu, sv[o], off);
    }
    int wid = t >> 5, lane = t & 31;
    if (lane == 0) {
        sred[wid][0] = se;
        #pragma unroll
        for (int o = 0; o < 16; o++) sred[wid][1+o] = sv[o];
    }
    __syncthreads();

    if (t < 32) {
        float tot = 0.f;
        if (t < 17) {
            #pragma unroll
            for (int w = 0; w < 16; w++) tot += sred[w][t];
        }
        float setot = __shfl_sync(0xffffffffu, tot, 0);
        float s = (t >= 1 && t < 17) ? (tot / setot) : 0.f;
        float s2 = s*s;
        #pragma unroll
        for (int off = 16; off > 0; off >>= 1)
            s2 += __shfl_xor_sync(0xffffffffu, s2, off);
        float scale = (s2 / (1.f + s2)) / sqrtf(s2 + 1e-8f);
        if (t >= 1 && t < 17) {
            float vv = scale * s;
            int o = t - 1;
            g_v[(b*NCLS + c)*OD + o] = vv;
            if (!last) g_vc[(b*NCLS + c)*OD + o] += vv;
        }
    }
}

// ---------------- head ----------------
__global__ void head_kernel(float* __restrict__ out)
{
    int b = blockIdx.x;
    int t = threadIdx.x;
    __shared__ float len[NCLS];
    if (t < NCLS) {
        float s = 0.f;
        #pragma unroll
        for (int o = 0; o < OD; o++) {
            float x = g_v[(b*NCLS + t)*OD + o];
            s = fmaf(x, x, s);
        }
        len[t] = sqrtf(s);
    }
    __syncthreads();
    if (t == 0) {
        int best = 0; float bv = len[0];
        #pragma unroll
        for (int c = 1; c < NCLS; c++)
            if (len[c] > bv) { bv = len[c]; best = c; }
        g_cls[b] = best;
    }
    __syncthreads();
    int best = g_cls[b];
    if (t < NCLS) {
        out[OUT_OHE_OFF + b*NCLS + t] = (t == best) ? 1.0f : 0.0f;
        out[OUT_LEN_OFF + b*NCLS + t] = len[t];
    }
}

// ---------------- decoder ----------------
__global__ void dec1_kernel(const float* __restrict__ w1, const float* __restrict__ b1)
{
    int idx = blockIdx.x*256 + threadIdx.x;
    if (idx >= BATCH*512) return;
    int j = idx % 512, b = idx / 512;
    int cls = g_cls[b];
    const float* v = &g_v[(b*NCLS + cls)*OD];
    float a = b1[j];
    #pragma unroll
    for (int d = 0; d < OD; d++)
        a = fmaf(v[d], w1[(size_t)(cls*OD + d)*512 + j], a);
    g_h1[idx] = fmaxf(a, 0.f);
}

__global__ void dec2_kernel(const float* __restrict__ w2, const float* __restrict__ b2)
{
    int idx = blockIdx.x*256 + threadIdx.x;
    if (idx >= BATCH*1024) return;
    int j = idx % 1024, b = idx / 1024;
    const float* h = &g_h1[b*512];
    float a = b2[j];
    #pragma unroll 4
    for (int k = 0; k < 512; k++)
        a = fmaf(h[k], w2[(size_t)k*1024 + j], a);
    g_h2[idx] = fmaxf(a, 0.f);
}

__global__ void dec3_kernel(const float* __restrict__ w3, const float* __restrict__ b3,
                            float* __restrict__ out)
{
    int idx = blockIdx.x*256 + threadIdx.x;
    if (idx >= BATCH*784) return;
    int p = idx % 784, b = idx / 784;
    const float* h = &g_h2[b*1024];
    float a = b3[p];
    #pragma unroll 4
    for (int k = 0; k < 1024; k++)
        a = fmaf(h[k], w3[(size_t)k*784 + p], a);
    out[OUT_REC_OFF + idx] = 1.f / (1.f + expf(-a));
}

// ---------------- launch ----------------
extern "C" void kernel_launch(void* const* d_in, const int* in_sizes, int n_in,
                              void* d_out, int out_size)
{
    const float* imgs    = (const float*)d_in[0];
    const float* conv1_w = (const float*)d_in[1];
    const float* conv1_b = (const float*)d_in[2];
    const float* conv2_w = (const float*)d_in[3];
    const float* conv2_b = (const float*)d_in[4];
    const float* W_digit = (const float*)d_in[5];
    const float* dec_w1  = (const float*)d_in[6];
    const float* dec_b1  = (const float*)d_in[7];
    const float* dec_w2  = (const float*)d_in[8];
    const float* dec_b2  = (const float*)d_in[9];
    const float* dec_w3  = (const float*)d_in[10];
    const float* dec_b3  = (const float*)d_in[11];
    float* out = (float*)d_out;

    cudaFuncSetAttribute(conv2_tc_kernel,
                         cudaFuncAttributeMaxDynamicSharedMemorySize, CONV2_SMEM);

    // prep (runs concurrently with conv1 in the graph stream order anyway)
    xoff_kernel<<<(KTOT + 255)/256, 256>>>();
    wsplit_kernel<<<dim3(KTOT/32, C2/32), 256>>>(conv2_w);

    conv1_kernel<<<dim3(C1, BATCH), 256>>>(imgs, conv1_w, conv1_b);
    conv2_tc_kernel<<<MTILES, 256, CONV2_SMEM>>>(conv2_b);
    squash_prim_kernel<<<(BATCH*NCAP + 255)/256, 256>>>();
    vc_zero_kernel<<<(BATCH*NCLS*OD + 255)/256, 256>>>();
    for (int it = 0; it < 3; it++)
        route_fused_kernel<<<dim3(NCLS, BATCH), 512>>>(W_digit, it == 2 ? 1 : 0);
    head_kernel<<<BATCH, 32>>>(out);
    dec1_kernel<<<(BATCH*512 + 255)/256, 256>>>(dec_w1, dec_b1);
    dec2_kernel<<<(BATCH*1024 + 255)/256, 256>>>(dec_w2, dec_b2);
    dec3_kernel<<<(BATCH*784 + 255)/256, 256>>>(dec_w3, dec_b3, out);
    (void)in_sizes; (void)n_in; (void)out_size;
}

// round 6
// speedup vs baseline: 1.6405x; 1.0618x over previous
#include <cuda_runtime.h>
#include <cuda_bf16.h>
#include <math.h>
#include <stdint.h>

// ---------------- problem constants ----------------
#define BATCH 128
#define C1 256
#define H1 20
#define C2 256
#define H2 12
#define NMAP 32
#define NPRIM 144
#define NCAP (NMAP*NPRIM)   // 4608
#define NCLS 10
#define OD 16
#define ID 8

#define OUT_OHE_OFF 0
#define OUT_REC_OFF (BATCH*NCLS)
#define OUT_LEN_OFF (BATCH*NCLS + BATCH*784)

// conv2 GEMM geometry
#define KTOT 20736          // 256*81
#define KC   64             // K per chunk
#define NBLK 324            // 20736/64
#define MTILES 144          // 18432/128

// ---------------- device scratch ----------------
__device__ float g_conv1[(size_t)BATCH*C1*H1*H1];
__device__ float g_p[(size_t)BATCH*C2*H2*H2];
__device__ float g_u[(size_t)BATCH*NCAP*ID];
__device__ float g_v[BATCH*NCLS*OD];
__device__ float g_vc[BATCH*NCLS*OD];
__device__ int   g_cls[BATCH];
__device__ float g_h1[BATCH*512];
__device__ float g_h2[BATCH*1024];
__device__ __nv_bfloat16 g_wth[(size_t)KTOT*C2];   // W^T hi plane [k][oc]
__device__ __nv_bfloat16 g_wtl[(size_t)KTOT*C2];   // W^T lo plane
__device__ int g_xoff[KTOT];                       // im2col offset table

// ---------------- small PTX helpers ----------------
__device__ __forceinline__ uint32_t smem_u32(const void* p) {
    uint32_t a;
    asm("{ .reg .u64 t; cvta.to.shared.u64 t, %1; cvt.u32.u64 %0, t; }"
        : "=r"(a) : "l"(p));
    return a;
}
__device__ __forceinline__ void ldsm4(uint32_t* r, uint32_t a) {
    asm volatile("ldmatrix.sync.aligned.m8n8.x4.shared.b16 {%0,%1,%2,%3}, [%4];"
        : "=r"(r[0]), "=r"(r[1]), "=r"(r[2]), "=r"(r[3]) : "r"(a));
}
__device__ __forceinline__ void ldsm4t(uint32_t* r, uint32_t a) {
    asm volatile("ldmatrix.sync.aligned.m8n8.x4.trans.shared.b16 {%0,%1,%2,%3}, [%4];"
        : "=r"(r[0]), "=r"(r[1]), "=r"(r[2]), "=r"(r[3]) : "r"(a));
}
__device__ __forceinline__ void mma_bf16(float* c, const uint32_t* a, const uint32_t* b) {
    asm volatile("mma.sync.aligned.m16n8k16.row.col.f32.bf16.bf16.f32 "
        "{%0,%1,%2,%3}, {%4,%5,%6,%7}, {%8,%9}, {%0,%1,%2,%3};"
        : "+f"(c[0]), "+f"(c[1]), "+f"(c[2]), "+f"(c[3])
        : "r"(a[0]), "r"(a[1]), "r"(a[2]), "r"(a[3]), "r"(b[0]), "r"(b[1]));
}
__device__ __forceinline__ void cp16(uint32_t dst, const void* src) {
    asm volatile("cp.async.ca.shared.global [%0], [%1], 16;"
                 :: "r"(dst), "l"(src) : "memory");
}
__device__ __forceinline__ void cp_commit() {
    asm volatile("cp.async.commit_group;" ::: "memory");
}
__device__ __forceinline__ void cp_wait0() {
    asm volatile("cp.async.wait_group 0;" ::: "memory");
}
// bf16 hi/lo split of two floats into packed bf16x2 regs
__device__ __forceinline__ void split2(float x0, float x1, uint32_t& hp, uint32_t& lp) {
    asm("cvt.rn.bf16x2.f32 %0, %1, %2;" : "=r"(hp) : "f"(x1), "f"(x0));
    float h0 = __uint_as_float(hp << 16);
    float h1 = __uint_as_float(hp & 0xFFFF0000u);
    asm("cvt.rn.bf16x2.f32 %0, %1, %2;" : "=r"(lp) : "f"(x1 - h1), "f"(x0 - h0));
}
static __device__ __forceinline__ uint32_t sw128(uint32_t off) {
    return off ^ ((off >> 3) & 0x70);
}

// smem layout inside each buffer
#define OFF_XH 0u
#define OFF_XL 16384u
#define OFF_WH 32768u
#define OFF_WL 65536u
#define BUF_BYTES 98304u
#define CONV2_SMEM (2u*BUF_BYTES)   // 196608 bytes

// ---------------- one-time prep kernels ----------------
__global__ void xoff_kernel()
{
    int q = blockIdx.x*256 + threadIdx.x;
    if (q >= KTOT) return;
    int ic = q / 81;
    int r  = q - ic*81;
    int ky = r / 9;
    int kx = r - ky*9;
    g_xoff[q] = ic*400 + ky*20 + kx;
}

// w2[oc][k] -> Wt_h/Wt_l [k][oc]  (tiled transpose + split)
__global__ __launch_bounds__(256) void wsplit_kernel(const float* __restrict__ w2)
{
    __shared__ float s[32][33];
    int kt = blockIdx.x;     // 648
    int ot = blockIdx.y;     // 8
    int tx = threadIdx.x & 31;
    int ty = threadIdx.x >> 5;   // 0..7
    #pragma unroll
    for (int j = 0; j < 4; j++) {
        int oc = ot*32 + ty + j*8;
        s[ty + j*8][tx] = w2[(size_t)oc*KTOT + kt*32 + tx];
    }
    __syncthreads();
    #pragma unroll
    for (int j = 0; j < 4; j++) {
        int k  = kt*32 + ty + j*8;
        int oc = ot*32 + tx;
        float v = s[tx][ty + j*8];
        __nv_bfloat16 h = __float2bfloat16(v);
        float hv = __bfloat162float(h);
        g_wth[(size_t)k*C2 + oc] = h;
        g_wtl[(size_t)k*C2 + oc] = __float2bfloat16(v - hv);
    }
}

// ---------------- conv2 tensor-core kernel (512 threads, 32x64 warp tile) ----------------
__global__ void __launch_bounds__(512, 1) conv2_tc_kernel(const float* __restrict__ b2)
{
    extern __shared__ char smem[];
    uint32_t sbase = smem_u32(smem);
    int t = threadIdx.x;
    int warp = t >> 5, lane = t & 31;
    int tile = blockIdx.x;

    int warp_m = warp >> 2;        // 0..3  (32 pos each)
    int warp_n = warp & 3;         // 0..3  (64 oc each)

    // X staging mapping: thread -> (pos, k-quarter)
    int spos = t >> 2;             // 0..127
    int kq   = (t & 3) * 16;       // 0,16,32,48
    int grow = tile*128 + spos;
    int bimg = grow / NPRIM;
    int posl = grow - bimg*NPRIM;
    int oy = posl / 12, ox = posl - (posl/12)*12;
    const float* actbase = g_conv1 + ((size_t)bimg*C1)*400 + oy*20 + ox;

    // W staging mapping: thread -> (plane, krow, 128B segment)
    int wplane = t >> 8;           // 0..1
    int wrem   = t & 255;
    int wkrow  = wrem >> 2;        // 0..63
    int wseg   = wrem & 3;         // 0..3 (64 oc each)
    const __nv_bfloat16* wplanep = wplane ? g_wtl : g_wth;
    uint32_t wdst_base = sbase + (wplane ? OFF_WL : OFF_WH) + (uint32_t)wkrow*512u;

    float acc[2][8][4];
    #pragma unroll
    for (int mt = 0; mt < 2; mt++)
        #pragma unroll
        for (int nt = 0; nt < 8; nt++)
            #pragma unroll
            for (int e = 0; e < 4; e++) acc[mt][nt][e] = 0.f;

    // prologue: stage chunk 0 into buf0
    {
        #pragma unroll
        for (int i = 0; i < 8; i++) {
            uint32_t dst = wdst_base + (uint32_t)((wseg*128 + i*16) ^ ((wkrow & 7) << 4));
            cp16(dst, wplanep + (size_t)wkrow*C2 + wseg*64 + i*8);
        }
        cp_commit();
        float xv[16];
        #pragma unroll
        for (int g = 0; g < 4; g++) {
            int4 off4 = *(const int4*)&g_xoff[kq + g*4];
            xv[g*4+0] = actbase[off4.x];
            xv[g*4+1] = actbase[off4.y];
            xv[g*4+2] = actbase[off4.z];
            xv[g*4+3] = actbase[off4.w];
        }
        #pragma unroll
        for (int c = 0; c < 2; c++) {
            uint32_t hp[4], lp[4];
            #pragma unroll
            for (int e = 0; e < 4; e++)
                split2(xv[c*8 + 2*e], xv[c*8 + 2*e + 1], hp[e], lp[e]);
            uint32_t boff = sw128((uint32_t)(spos*128 + kq*2 + c*16));
            *(uint4*)(smem + OFF_XH + boff) = make_uint4(hp[0], hp[1], hp[2], hp[3]);
            *(uint4*)(smem + OFF_XL + boff) = make_uint4(lp[0], lp[1], lp[2], lp[3]);
        }
        cp_wait0();
    }
    __syncthreads();

    for (int kb = 0; kb < NBLK; kb++) {
        uint32_t cur = (uint32_t)(kb & 1) * BUF_BYTES;
        uint32_t nxt = BUF_BYTES - cur;
        bool have_next = (kb + 1 < NBLK);

        float xv[16];
        if (have_next) {
            // W cp.async for kb+1
            const __nv_bfloat16* wsrc = wplanep + (size_t)((kb+1)*KC + wkrow)*C2 + wseg*64;
            uint32_t wd = wdst_base + nxt;
            #pragma unroll
            for (int i = 0; i < 8; i++) {
                uint32_t dst = wd + (uint32_t)((wseg*128 + i*16) ^ ((wkrow & 7) << 4));
                cp16(dst, wsrc + i*8);
            }
            cp_commit();
            // X gather for kb+1
            #pragma unroll
            for (int g = 0; g < 4; g++) {
                int4 off4 = *(const int4*)&g_xoff[(kb+1)*KC + kq + g*4];
                xv[g*4+0] = actbase[off4.x];
                xv[g*4+1] = actbase[off4.y];
                xv[g*4+2] = actbase[off4.z];
                xv[g*4+3] = actbase[off4.w];
            }
        }

        // ---- compute chunk kb from buf cur ----
        #pragma unroll
        for (int kk = 0; kk < 4; kk++) {
            uint32_t bh[8][2], bl[8][2];
            #pragma unroll
            for (int np = 0; np < 4; np++) {
                int j = lane >> 3, rw = lane & 7;
                int krow = kk*16 + (j & 1)*8 + rw;
                int ncol = warp_n*64 + np*16 + (j >> 1)*8;
                uint32_t byte = (uint32_t)(krow*512 + ((ncol*2) ^ ((krow & 7) << 4)));
                uint32_t r[4];
                ldsm4t(r, sbase + cur + OFF_WH + byte);
                bh[2*np][0] = r[0]; bh[2*np][1] = r[1];
                bh[2*np+1][0] = r[2]; bh[2*np+1][1] = r[3];
                ldsm4t(r, sbase + cur + OFF_WL + byte);
                bl[2*np][0] = r[0]; bl[2*np][1] = r[1];
                bl[2*np+1][0] = r[2]; bl[2*np+1][1] = r[3];
            }
            #pragma unroll
            for (int mt = 0; mt < 2; mt++) {
                int rowl = warp_m*32 + mt*16 + (lane & 15);
                uint32_t abyte = sw128((uint32_t)(rowl*128 + (kk*16 + (lane >> 4)*8)*2));
                uint32_t ah[4], al[4];
                ldsm4(ah, sbase + cur + OFF_XH + abyte);
                ldsm4(al, sbase + cur + OFF_XL + abyte);
                #pragma unroll
                for (int nt = 0; nt < 8; nt++) {
                    mma_bf16(acc[mt][nt], ah, bh[nt]);
                    mma_bf16(acc[mt][nt], ah, bl[nt]);
                    mma_bf16(acc[mt][nt], al, bh[nt]);
                }
            }
        }

        if (have_next) {
            #pragma unroll
            for (int c = 0; c < 2; c++) {
                uint32_t hp[4], lp[4];
                #pragma unroll
                for (int e = 0; e < 4; e++)
                    split2(xv[c*8 + 2*e], xv[c*8 + 2*e + 1], hp[e], lp[e]);
                uint32_t boff = sw128((uint32_t)(spos*128 + kq*2 + c*16));
                *(uint4*)(smem + nxt + OFF_XH + boff) = make_uint4(hp[0], hp[1], hp[2], hp[3]);
                *(uint4*)(smem + nxt + OFF_XL + boff) = make_uint4(lp[0], lp[1], lp[2], lp[3]);
            }
            cp_wait0();
        }
        __syncthreads();
    }

    // ---- epilogue: write D + bias to g_p ----
    #pragma unroll
    for (int mt = 0; mt < 2; mt++) {
        int pr0 = tile*128 + warp_m*32 + mt*16 + (lane >> 2);
        #pragma unroll
        for (int half = 0; half < 2; half++) {
            int pr = pr0 + half*8;
            int b = pr / NPRIM;
            int pl = pr - b*NPRIM;
            #pragma unroll
            for (int nt = 0; nt < 8; nt++) {
                int oc = warp_n*64 + nt*8 + (lane & 3)*2;
                float c0 = acc[mt][nt][half*2 + 0];
                float c1 = acc[mt][nt][half*2 + 1];
                g_p[((size_t)b*C2 + oc)*NPRIM + pl]     = c0 + __ldg(&b2[oc]);
                g_p[((size_t)b*C2 + oc + 1)*NPRIM + pl] = c1 + __ldg(&b2[oc+1]);
            }
        }
    }
}

// ---------------- conv1 + relu ----------------
__global__ __launch_bounds__(256) void conv1_kernel(
    const float* __restrict__ img, const float* __restrict__ w,
    const float* __restrict__ bias)
{
    int oc = blockIdx.x, b = blockIdx.y;
    __shared__ float si[28*28];
    __shared__ float sw[81];
    int t = threadIdx.x;
    for (int i = t; i < 784; i += 256) si[i] = img[b*784 + i];
    if (t < 81) sw[t] = w[oc*81 + t];
    __syncthreads();
    float bs = bias[oc];
    for (int p = t; p < 400; p += 256) {
        int oy = p / 20, ox = p % 20;
        float a = 0.f;
        #pragma unroll
        for (int ky = 0; ky < 9; ky++)
            #pragma unroll
            for (int kx = 0; kx < 9; kx++)
                a = fmaf(sw[ky*9+kx], si[(oy+ky)*28 + ox + kx], a);
        a += bs;
        g_conv1[(((size_t)b*C1 + oc)*H1 + oy)*H1 + ox] = fmaxf(a, 0.f);
    }
}

// ---------------- primary capsule squash ----------------
__global__ void squash_prim_kernel()
{
    int idx = blockIdx.x*blockDim.x + threadIdx.x;
    if (idx >= BATCH*NCAP) return;
    int pos = idx % NPRIM;
    int m   = (idx / NPRIM) % NMAP;
    int b   = idx / NCAP;
    float x[ID]; float s2 = 0.f;
    #pragma unroll
    for (int d = 0; d < ID; d++) {
        x[d] = g_p[(((size_t)b*C2 + d*NMAP + m)*NPRIM) + pos];
        s2 = fmaf(x[d], x[d], s2);
    }
    float scale = (s2 / (1.f + s2)) / sqrtf(s2 + 1e-8f);
    float* up = g_u + (size_t)idx*ID;
    #pragma unroll
    for (int d = 0; d < ID; d++) up[d] = scale * x[d];
}

// ---------------- fused routing ----------------
__global__ void vc_zero_kernel()
{
    int idx = blockIdx.x*256 + threadIdx.x;
    if (idx < BATCH*NCLS*OD) g_vc[idx] = 0.f;
}

__global__ __launch_bounds__(512) void route_fused_kernel(
    const float* __restrict__ Wd, int last)
{
    int c = blockIdx.x, b = blockIdx.y;
    int t = threadIdx.x;
    __shared__ float sVc[16];
    __shared__ float sred[16][18];

    if (t < 16) sVc[t] = g_vc[(b*NCLS + c)*OD + t];
    __syncthreads();
    float Vc[16];
    #pragma unroll
    for (int o = 0; o < 16; o++) Vc[o] = sVc[o];

    float se = 0.f;
    float sv[16];
    #pragma unroll
    for (int o = 0; o < 16; o++) sv[o] = 0.f;

    #pragma unroll 1
    for (int j = 0; j < 9; j++) {
        int n = t + j*512;
        const float4* u4 = (const float4*)&g_u[((size_t)b*NCAP + n)*ID];
        float4 ua = u4[0], ub = u4[1];
        const float4* wp = (const float4*)&Wd[((size_t)n*NCLS + c)*OD*ID];
        float uh[16];
        float bcur = 0.f;
        #pragma unroll
        for (int o = 0; o < 16; o++) {
            float4 w0 = wp[2*o], w1 = wp[2*o+1];
            float a = w0.x*ua.x;
            a = fmaf(w0.y, ua.y, a); a = fmaf(w0.z, ua.z, a);
            a = fmaf(w0.w, ua.w, a); a = fmaf(w1.x, ub.x, a);
            a = fmaf(w1.y, ub.y, a); a = fmaf(w1.z, ub.z, a);
            a = fmaf(w1.w, ub.w, a);
            uh[o] = a;
            bcur = fmaf(a, Vc[o], bcur);
        }
        float e = __expf(bcur);
        se += e;
        #pragma unroll
        for (int o = 0; o < 16; o++) sv[o] = fmaf(e, uh[o], sv[o]);
    }

    #pragma unroll
    for (int off = 16; off > 0; off >>= 1) {
        se += __shfl_down_sync(0xffffffffu, se, off);
        #pragma unroll
        for (int o = 0; o < 16; o++)
            sv[o] += __shfl_down_sync(0xffffffffu, sv[o], off);
    }
    int wid = t >> 5, lane = t & 31;
    if (lane == 0) {
        sred[wid][0] = se;
        #pragma unroll
        for (int o = 0; o < 16; o++) sred[wid][1+o] = sv[o];
    }
    __syncthreads();

    if (t < 32) {
        float tot = 0.f;
        if (t < 17) {
            #pragma unroll
            for (int w = 0; w < 16; w++) tot += sred[w][t];
        }
        float setot = __shfl_sync(0xffffffffu, tot, 0);
        float s = (t >= 1 && t < 17) ? (tot / setot) : 0.f;
        float s2 = s*s;
        #pragma unroll
        for (int off = 16; off > 0; off >>= 1)
            s2 += __shfl_xor_sync(0xffffffffu, s2, off);
        float scale = (s2 / (1.f + s2)) / sqrtf(s2 + 1e-8f);
        if (t >= 1 && t < 17) {
            float vv = scale * s;
            int o = t - 1;
            g_v[(b*NCLS + c)*OD + o] = vv;
            if (!last) g_vc[(b*NCLS + c)*OD + o] += vv;
        }
    }
}

// ---------------- head ----------------
__global__ void head_kernel(float* __restrict__ out)
{
    int b = blockIdx.x;
    int t = threadIdx.x;
    __shared__ float len[NCLS];
    if (t < NCLS) {
        float s = 0.f;
        #pragma unroll
        for (int o = 0; o < OD; o++) {
            float x = g_v[(b*NCLS + t)*OD + o];
            s = fmaf(x, x, s);
        }
        len[t] = sqrtf(s);
    }
    __syncthreads();
    if (t == 0) {
        int best = 0; float bv = len[0];
        #pragma unroll
        for (int c = 1; c < NCLS; c++)
            if (len[c] > bv) { bv = len[c]; best = c; }
        g_cls[b] = best;
    }
    __syncthreads();
    int best = g_cls[b];
    if (t < NCLS) {
        out[OUT_OHE_OFF + b*NCLS + t] = (t == best) ? 1.0f : 0.0f;
        out[OUT_LEN_OFF + b*NCLS + t] = len[t];
    }
}

// ---------------- decoder ----------------
__global__ void dec1_kernel(const float* __restrict__ w1, const float* __restrict__ b1)
{
    int idx = blockIdx.x*256 + threadIdx.x;
    if (idx >= BATCH*512) return;
    int j = idx % 512, b = idx / 512;
    int cls = g_cls[b];
    const float* v = &g_v[(b*NCLS + cls)*OD];
    float a = b1[j];
    #pragma unroll
    for (int d = 0; d < OD; d++)
        a = fmaf(v[d], w1[(size_t)(cls*OD + d)*512 + j], a);
    g_h1[idx] = fmaxf(a, 0.f);
}

__global__ void dec2_kernel(const float* __restrict__ w2, const float* __restrict__ b2)
{
    int idx = blockIdx.x*256 + threadIdx.x;
    if (idx >= BATCH*1024) return;
    int j = idx % 1024, b = idx / 1024;
    const float* h = &g_h1[b*512];
    float a = b2[j];
    #pragma unroll 4
    for (int k = 0; k < 512; k++)
        a = fmaf(h[k], w2[(size_t)k*1024 + j], a);
    g_h2[idx] = fmaxf(a, 0.f);
}

__global__ void dec3_kernel(const float* __restrict__ w3, const float* __restrict__ b3,
                            float* __restrict__ out)
{
    int idx = blockIdx.x*256 + threadIdx.x;
    if (idx >= BATCH*784) return;
    int p = idx % 784, b = idx / 784;
    const float* h = &g_h2[b*1024];
    float a = b3[p];
    #pragma unroll 4
    for (int k = 0; k < 1024; k++)
        a = fmaf(h[k], w3[(size_t)k*784 + p], a);
    out[OUT_REC_OFF + idx] = 1.f / (1.f + expf(-a));
}

// ---------------- launch ----------------
extern "C" void kernel_launch(void* const* d_in, const int* in_sizes, int n_in,
                              void* d_out, int out_size)
{
    const float* imgs    = (const float*)d_in[0];
    const float* conv1_w = (const float*)d_in[1];
    const float* conv1_b = (const float*)d_in[2];
    const float* conv2_w = (const float*)d_in[3];
    const float* conv2_b = (const float*)d_in[4];
    const float* W_digit = (const float*)d_in[5];
    const float* dec_w1  = (const float*)d_in[6];
    const float* dec_b1  = (const float*)d_in[7];
    const float* dec_w2  = (const float*)d_in[8];
    const float* dec_b2  = (const float*)d_in[9];
    const float* dec_w3  = (const float*)d_in[10];
    const float* dec_b3  = (const float*)d_in[11];
    float* out = (float*)d_out;

    cudaFuncSetAttribute(conv2_tc_kernel,
                         cudaFuncAttributeMaxDynamicSharedMemorySize, CONV2_SMEM);

    xoff_kernel<<<(KTOT + 255)/256, 256>>>();
    wsplit_kernel<<<dim3(KTOT/32, C2/32), 256>>>(conv2_w);

    conv1_kernel<<<dim3(C1, BATCH), 256>>>(imgs, conv1_w, conv1_b);
    conv2_tc_kernel<<<MTILES, 512, CONV2_SMEM>>>(conv2_b);
    squash_prim_kernel<<<(BATCH*NCAP + 255)/256, 256>>>();
    vc_zero_kernel<<<(BATCH*NCLS*OD + 255)/256, 256>>>();
    for (int it = 0; it < 3; it++)
        route_fused_kernel<<<dim3(NCLS, BATCH), 512>>>(W_digit, it == 2 ? 1 : 0);
    head_kernel<<<BATCH, 32>>>(out);
    dec1_kernel<<<(BATCH*512 + 255)/256, 256>>>(dec_w1, dec_b1);
    dec2_kernel<<<(BATCH*1024 + 255)/256, 256>>>(dec_w2, dec_b2);
    dec3_kernel<<<(BATCH*784 + 255)/256, 256>>>(dec_w3, dec_b3, out);
    (void)in_sizes; (void)n_in; (void)out_size;
}

// round 8
// speedup vs baseline: 2.5153x; 1.5333x over previous
#include <cuda_runtime.h>
#include <cuda_bf16.h>
#include <cuda_fp16.h>
#include <math.h>
#include <stdint.h>

// ---------------- problem constants ----------------
#define BATCH 128
#define C1 256
#define H1 20
#define C2 256
#define H2 12
#define NMAP 32
#define NPRIM 144
#define NCAP (NMAP*NPRIM)   // 4608
#define NCLS 10
#define OD 16
#define ID 8

#define OUT_OHE_OFF 0
#define OUT_REC_OFF (BATCH*NCLS)
#define OUT_LEN_OFF (BATCH*NCLS + BATCH*784)

// conv2 GEMM geometry (K reordered: k' = (ky*9+kx)*256 + ic)
#define KTOT 20736
#define KC   64
#define NBLK 324
#define MTILES 144

// ---------------- device scratch ----------------
__device__ float g_conv1[(size_t)BATCH*C1*400];
__device__ __nv_bfloat16 g_xh[(size_t)BATCH*400*C1];   // NHWC hi plane
__device__ __nv_bfloat16 g_xl[(size_t)BATCH*400*C1];   // NHWC lo plane
__device__ float g_p[(size_t)BATCH*C2*NPRIM];
__device__ float g_u[(size_t)BATCH*NCAP*ID];
__device__ __half g_uh16[(size_t)BATCH*NCAP*NCLS*OD];  // 188MB fp16 u_hat
__device__ float g_v[BATCH*NCLS*OD];
__device__ float g_vc[BATCH*NCLS*OD];
__device__ int   g_cls[BATCH];
__device__ float g_h1[BATCH*512];
__device__ float g_h2[BATCH*1024];
__device__ __nv_bfloat16 g_wth[(size_t)KTOT*C2];   // W^T hi [k'][oc]
__device__ __nv_bfloat16 g_wtl[(size_t)KTOT*C2];   // W^T lo

// ---------------- small PTX helpers ----------------
__device__ __forceinline__ uint32_t smem_u32(const void* p) {
    uint32_t a;
    asm("{ .reg .u64 t; cvta.to.shared.u64 t, %1; cvt.u32.u64 %0, t; }"
        : "=r"(a) : "l"(p));
    return a;
}
__device__ __forceinline__ void ldsm4(uint32_t* r, uint32_t a) {
    asm volatile("ldmatrix.sync.aligned.m8n8.x4.shared.b16 {%0,%1,%2,%3}, [%4];"
        : "=r"(r[0]), "=r"(r[1]), "=r"(r[2]), "=r"(r[3]) : "r"(a));
}
__device__ __forceinline__ void ldsm4t(uint32_t* r, uint32_t a) {
    asm volatile("ldmatrix.sync.aligned.m8n8.x4.trans.shared.b16 {%0,%1,%2,%3}, [%4];"
        : "=r"(r[0]), "=r"(r[1]), "=r"(r[2]), "=r"(r[3]) : "r"(a));
}
__device__ __forceinline__ void mma_bf16(float* c, const uint32_t* a, const uint32_t* b) {
    asm volatile("mma.sync.aligned.m16n8k16.row.col.f32.bf16.bf16.f32 "
        "{%0,%1,%2,%3}, {%4,%5,%6,%7}, {%8,%9}, {%0,%1,%2,%3};"
        : "+f"(c[0]), "+f"(c[1]), "+f"(c[2]), "+f"(c[3])
        : "r"(a[0]), "r"(a[1]), "r"(a[2]), "r"(a[3]), "r"(b[0]), "r"(b[1]));
}
__device__ __forceinline__ void cp16(uint32_t dst, const void* src) {
    asm volatile("cp.async.ca.shared.global [%0], [%1], 16;"
                 :: "r"(dst), "l"(src) : "memory");
}
__device__ __forceinline__ void cp_commit() {
    asm volatile("cp.async.commit_group;" ::: "memory");
}
__device__ __forceinline__ void cp_wait0() {
    asm volatile("cp.async.wait_group 0;" ::: "memory");
}
static __device__ __forceinline__ uint32_t sw128(uint32_t off) {
    return off ^ ((off >> 3) & 0x70);
}

// smem layout inside each buffer (identical to proven R6 layout)
#define OFF_XH 0u
#define OFF_XL 16384u
#define OFF_WH 32768u
#define OFF_WL 65536u
#define BUF_BYTES 98304u
#define CONV2_SMEM (2u*BUF_BYTES)

// ---------------- conv1 + relu ----------------
__global__ __launch_bounds__(256) void conv1_kernel(
    const float* __restrict__ img, const float* __restrict__ w,
    const float* __restrict__ bias)
{
    int oc = blockIdx.x, b = blockIdx.y;
    __shared__ float si[28*28];
    __shared__ float sw[81];
    int t = threadIdx.x;
    for (int i = t; i < 784; i += 256) si[i] = img[b*784 + i];
    if (t < 81) sw[t] = w[oc*81 + t];
    __syncthreads();
    float bs = bias[oc];
    for (int p = t; p < 400; p += 256) {
        int oy = p / 20, ox = p % 20;
        float a = 0.f;
        #pragma unroll
        for (int ky = 0; ky < 9; ky++)
            #pragma unroll
            for (int kx = 0; kx < 9; kx++)
                a = fmaf(sw[ky*9+kx], si[(oy+ky)*28 + ox + kx], a);
        a += bs;
        g_conv1[((size_t)(b*C1 + oc))*400 + oy*20 + ox] = fmaxf(a, 0.f);
    }
}

// ---------------- conv1 NCHW fp32 -> NHWC bf16 hi/lo planes ----------------
__global__ __launch_bounds__(512) void xpose_kernel()
{
    __shared__ uint32_t s[400*17];
    int b = blockIdx.x;
    int t = threadIdx.x;
    for (int c0 = 0; c0 < 256; c0 += 16) {
        __syncthreads();
        for (int i = t; i < 16*400; i += 512) {
            int c = i / 400, px = i - c*400;
            float v = g_conv1[((size_t)(b*C1 + c0 + c))*400 + px];
            __nv_bfloat16 h = __float2bfloat16(v);
            __nv_bfloat16 l = __float2bfloat16(v - __bfloat162float(h));
            uint32_t pk = (uint32_t)__bfloat16_as_ushort(h)
                        | ((uint32_t)__bfloat16_as_ushort(l) << 16);
            s[px*17 + c] = pk;
        }
        __syncthreads();
        for (int i = t; i < 400*16; i += 512) {
            int px = i >> 4, c = i & 15;
            uint32_t pk = s[px*17 + c];
            size_t o = ((size_t)b*400 + px)*256 + c0 + c;
            g_xh[o] = __ushort_as_bfloat16((unsigned short)(pk & 0xFFFFu));
            g_xl[o] = __ushort_as_bfloat16((unsigned short)(pk >> 16));
        }
    }
}

// ---------------- W transpose + split into k' = (r*256+ic) order ----------------
__global__ __launch_bounds__(256) void wsplit_kernel(const float* __restrict__ w2)
{
    __shared__ float s[8][32][33];
    int ic0 = blockIdx.x * 32, oc0 = blockIdx.y * 32;
    int t = threadIdx.x;
    for (int rc = 0; rc < 81; rc += 8) {
        int rcnt = min(8, 81 - rc);
        __syncthreads();
        #pragma unroll
        for (int pp = 0; pp < 4; pp++) {
            int pair = t + pp*256;
            int icl = pair & 31, ocl = pair >> 5;
            const float* src = w2 + (size_t)(oc0+ocl)*KTOT + (size_t)(ic0+icl)*81 + rc;
            for (int rr = 0; rr < rcnt; rr++)
                s[rr][icl][ocl] = src[rr];
        }
        __syncthreads();
        for (int rr = 0; rr < rcnt; rr++) {
            #pragma unroll
            for (int pp = 0; pp < 4; pp++) {
                int pair = t + pp*256;
                int ocl = pair & 31, icl = pair >> 5;
                float v = s[rr][icl][ocl];
                __nv_bfloat16 h = __float2bfloat16(v);
                size_t kk = (size_t)(rc+rr)*256 + ic0 + icl;
                g_wth[kk*C2 + oc0 + ocl] = h;
                g_wtl[kk*C2 + oc0 + ocl] = __float2bfloat16(v - __bfloat162float(h));
            }
        }
    }
}

// ---------------- conv2 tensor-core kernel (all-cp.async staging) ----------------
__global__ void __launch_bounds__(512, 1) conv2_tc_kernel(const float* __restrict__ b2)
{
    extern __shared__ char smem[];
    uint32_t sbase = smem_u32(smem);
    int t = threadIdx.x;
    int warp = t >> 5, lane = t & 31;
    int tile = blockIdx.x;

    int warp_m = warp >> 2;        // 0..3
    int warp_n = warp & 3;         // 0..3

    // X staging mapping: thread -> (row, seg quarter)
    int xrow = t >> 2;             // 0..127
    int xq   = t & 3;              // segs {xq, xq+4}
    int grow = tile*128 + xrow;
    int bimg = grow / NPRIM;
    int posl = grow - bimg*NPRIM;
    int oy = posl / 12, ox = posl - (posl/12)*12;
    int xb = bimg*400;

    // W staging mapping
    int wplane = t >> 8;
    int wrem   = t & 255;
    int wkrow  = wrem >> 2;
    int wseg   = wrem & 3;
    const __nv_bfloat16* wplanep = wplane ? g_wtl : g_wth;
    uint32_t wdst_base = sbase + (wplane ? OFF_WL : OFF_WH) + (uint32_t)wkrow*512u;

    float acc[2][8][4];
    #pragma unroll
    for (int mt = 0; mt < 2; mt++)
        #pragma unroll
        for (int nt = 0; nt < 8; nt++)
            #pragma unroll
            for (int e = 0; e < 4; e++) acc[mt][nt][e] = 0.f;

    // prologue: stage chunk 0 into buf0 (r=0 -> ky=0,kx=0, ic0=0)
    {
        #pragma unroll
        for (int i = 0; i < 8; i++) {
            uint32_t dst = wdst_base + (uint32_t)((wseg*128 + i*16) ^ ((wkrow & 7) << 4));
            cp16(dst, wplanep + (size_t)wkrow*C2 + wseg*64 + i*8);
        }
        size_t xsrcoff = ((size_t)(xb + oy*20 + ox))*256;
        uint32_t xdst = sbase + (uint32_t)xrow*128u;
        #pragma unroll
        for (int pl = 0; pl < 2; pl++) {
            const __nv_bfloat16* src = (pl ? g_xl : g_xh) + xsrcoff;
            uint32_t db = xdst + (pl ? OFF_XL : OFF_XH);
            #pragma unroll
            for (int ii = 0; ii < 2; ii++) {
                int s = xq + ii*4;
                cp16(db + (uint32_t)((s*16) ^ ((xrow & 7) << 4)), src + s*8);
            }
        }
        cp_commit();
        cp_wait0();
    }
    __syncthreads();

    for (int kb = 0; kb < NBLK; kb++) {
        uint32_t cur = (uint32_t)(kb & 1) * BUF_BYTES;
        uint32_t nxt = BUF_BYTES - cur;
        bool have_next = (kb + 1 < NBLK);

        if (have_next) {
            int kn = kb + 1;
            const __nv_bfloat16* wsrc = wplanep + (size_t)(kn*KC + wkrow)*C2 + wseg*64;
            uint32_t wd = wdst_base + nxt;
            #pragma unroll
            for (int i = 0; i < 8; i++) {
                uint32_t dst = wd + (uint32_t)((wseg*128 + i*16) ^ ((wkrow & 7) << 4));
                cp16(dst, wsrc + i*8);
            }
            int r = kn >> 2;
            int ky = r / 9, kx = r - ky*9;
            int ic0 = (kn & 3) * 64;
            size_t xsrcoff = ((size_t)(xb + (oy+ky)*20 + ox + kx))*256 + ic0;
            uint32_t xdst = sbase + nxt + (uint32_t)xrow*128u;
            #pragma unroll
            for (int pl = 0; pl < 2; pl++) {
                const __nv_bfloat16* src = (pl ? g_xl : g_xh) + xsrcoff;
                uint32_t db = xdst + (pl ? OFF_XL : OFF_XH);
                #pragma unroll
                for (int ii = 0; ii < 2; ii++) {
                    int s = xq + ii*4;
                    cp16(db + (uint32_t)((s*16) ^ ((xrow & 7) << 4)), src + s*8);
                }
            }
            cp_commit();
        }

        // ---- compute chunk kb from buf cur (identical to proven R6 core) ----
        #pragma unroll
        for (int kk = 0; kk < 4; kk++) {
            uint32_t bh[8][2], bl[8][2];
            #pragma unroll
            for (int np = 0; np < 4; np++) {
                int j = lane >> 3, rw = lane & 7;
                int krow = kk*16 + (j & 1)*8 + rw;
                int ncol = warp_n*64 + np*16 + (j >> 1)*8;
                uint32_t byte = (uint32_t)(krow*512 + ((ncol*2) ^ ((krow & 7) << 4)));
                uint32_t r[4];
                ldsm4t(r, sbase + cur + OFF_WH + byte);
                bh[2*np][0] = r[0]; bh[2*np][1] = r[1];
                bh[2*np+1][0] = r[2]; bh[2*np+1][1] = r[3];
                ldsm4t(r, sbase + cur + OFF_WL + byte);
                bl[2*np][0] = r[0]; bl[2*np][1] = r[1];
                bl[2*np+1][0] = r[2]; bl[2*np+1][1] = r[3];
            }
            #pragma unroll
            for (int mt = 0; mt < 2; mt++) {
                int rowl = warp_m*32 + mt*16 + (lane & 15);
                uint32_t abyte = sw128((uint32_t)(rowl*128 + (kk*16 + (lane >> 4)*8)*2));
                uint32_t ah[4], al[4];
                ldsm4(ah, sbase + cur + OFF_XH + abyte);
                ldsm4(al, sbase + cur + OFF_XL + abyte);
                #pragma unroll
                for (int nt = 0; nt < 8; nt++) {
                    mma_bf16(acc[mt][nt], ah, bh[nt]);
                    mma_bf16(acc[mt][nt], ah, bl[nt]);
                    mma_bf16(acc[mt][nt], al, bh[nt]);
                }
            }
        }

        if (have_next) cp_wait0();
        __syncthreads();
    }

    // ---- epilogue: write D + bias to g_p ----
    #pragma unroll
    for (int mt = 0; mt < 2; mt++) {
        int pr0 = tile*128 + warp_m*32 + mt*16 + (lane >> 2);
        #pragma unroll
        for (int half = 0; half < 2; half++) {
            int pr = pr0 + half*8;
            int b = pr / NPRIM;
            int pl = pr - b*NPRIM;
            #pragma unroll
            for (int nt = 0; nt < 8; nt++) {
                int oc = warp_n*64 + nt*8 + (lane & 3)*2;
                float c0 = acc[mt][nt][half*2 + 0];
                float c1 = acc[mt][nt][half*2 + 1];
                g_p[((size_t)b*C2 + oc)*NPRIM + pl]     = c0 + __ldg(&b2[oc]);
                g_p[((size_t)b*C2 + oc + 1)*NPRIM + pl] = c1 + __ldg(&b2[oc+1]);
            }
        }
    }
}

// ---------------- primary capsule squash ----------------
__global__ void squash_prim_kernel()
{
    int idx = blockIdx.x*blockDim.x + threadIdx.x;
    if (idx >= BATCH*NCAP) return;
    int pos = idx % NPRIM;
    int m   = (idx / NPRIM) % NMAP;
    int b   = idx / NCAP;
    float x[ID]; float s2 = 0.f;
    #pragma unroll
    for (int d = 0; d < ID; d++) {
        x[d] = g_p[(((size_t)b*C2 + d*NMAP + m)*NPRIM) + pos];
        s2 = fmaf(x[d], x[d], s2);
    }
    float scale = (s2 / (1.f + s2)) / sqrtf(s2 + 1e-8f);
    float* up = g_u + (size_t)idx*ID;
    #pragma unroll
    for (int d = 0; d < ID; d++) up[d] = scale * x[d];
}

// ---------------- u_hat materialization (fp16) ----------------
// thread = (n within 4-tile, co); W row lives in registers; loop over b.
__global__ __launch_bounds__(640) void uhat16_kernel(const float* __restrict__ Wd)
{
    int t = threadIdx.x;
    int co = t % 160, nl = t / 160;
    int n = blockIdx.x*4 + nl;
    const float4* wr = (const float4*)(Wd + ((size_t)n*160 + co)*8);
    float4 w0 = wr[0], w1 = wr[1];
    __half* outp = g_uh16 + (size_t)n*160 + co;
    const float4* up = (const float4*)(g_u + (size_t)n*8);
    #pragma unroll 4
    for (int b = 0; b < BATCH; b++) {
        float4 ua = __ldg(up), ub = __ldg(up + 1);
        float a = w0.x*ua.x;
        a = fmaf(w0.y, ua.y, a); a = fmaf(w0.z, ua.z, a); a = fmaf(w0.w, ua.w, a);
        a = fmaf(w1.x, ub.x, a); a = fmaf(w1.y, ub.y, a);
        a = fmaf(w1.z, ub.z, a); a = fmaf(w1.w, ub.w, a);
        outp[(size_t)b*NCAP*160] = __float2half_rn(a);
        up += NCAP*8/4;
    }
}

// ---------------- routing from materialized fp16 u_hat ----------------
__global__ void vc_zero_kernel()
{
    int idx = blockIdx.x*256 + threadIdx.x;
    if (idx < BATCH*NCLS*OD) g_vc[idx] = 0.f;
}

__device__ __forceinline__ void unpack8(const uint4& q, float* f) {
    const __half2* h = (const __half2*)&q;
    #pragma unroll
    for (int j = 0; j < 4; j++) {
        float2 v = __half22float2(h[j]);
        f[2*j] = v.x; f[2*j+1] = v.y;
    }
}

__global__ __launch_bounds__(512) void route16_kernel(int last)
{
    int cp = blockIdx.x;     // class pair 0..4 -> classes 2cp, 2cp+1
    int b  = blockIdx.y;
    int t  = threadIdx.x;
    __shared__ float sVc[32];
    __shared__ float sred[16][34];
    __shared__ float sfin[34];

    if (t < 32) sVc[t] = g_vc[(b*NCLS + 2*cp + (t >> 4))*OD + (t & 15)];
    __syncthreads();
    float Vc0[16], Vc1[16];
    #pragma unroll
    for (int o = 0; o < 16; o++) { Vc0[o] = sVc[o]; Vc1[o] = sVc[16+o]; }

    float se0 = 0.f, se1 = 0.f;
    float sv0[16], sv1[16];
    #pragma unroll
    for (int o = 0; o < 16; o++) { sv0[o] = 0.f; sv1[o] = 0.f; }

    #pragma unroll 1
    for (int j = 0; j < 9; j++) {
        int n = t + j*512;
        const uint4* up = (const uint4*)(g_uh16 + ((size_t)b*NCAP + n)*160 + cp*32);
        uint4 q0 = up[0], q1 = up[1], q2 = up[2], q3 = up[3];
        float uh0[16], uh1[16];
        unpack8(q0, uh0); unpack8(q1, uh0+8);
        unpack8(q2, uh1); unpack8(q3, uh1+8);
        float b0 = 0.f, b1 = 0.f;
        #pragma unroll
        for (int o = 0; o < 16; o++) {
            b0 = fmaf(uh0[o], Vc0[o], b0);
            b1 = fmaf(uh1[o], Vc1[o], b1);
        }
        float e0 = __expf(b0), e1 = __expf(b1);
        se0 += e0; se1 += e1;
        #pragma unroll
        for (int o = 0; o < 16; o++) {
            sv0[o] = fmaf(e0, uh0[o], sv0[o]);
            sv1[o] = fmaf(e1, uh1[o], sv1[o]);
        }
    }

    #pragma unroll
    for (int off = 16; off > 0; off >>= 1) {
        se0 += __shfl_down_sync(0xffffffffu, se0, off);
        se1 += __shfl_down_sync(0xffffffffu, se1, off);
        #pragma unroll
        for (int o = 0; o < 16; o++) {
            sv0[o] += __shfl_down_sync(0xffffffffu, sv0[o], off);
            sv1[o] += __shfl_down_sync(0xffffffffu, sv1[o], off);
        }
    }
    int wid = t >> 5, lane = t & 31;
    if (lane == 0) {
        sred[wid][0] = se0;
        sred[wid][17] = se1;
        #pragma unroll
        for (int o = 0; o < 16; o++) {
            sred[wid][1+o] = sv0[o];
            sred[wid][18+o] = sv1[o];
        }
    }
    __syncthreads();

    if (t < 34) {
        float tot = 0.f;
        #pragma unroll
        for (int w = 0; w < 16; w++) tot += sred[w][t];
        sfin[t] = tot;
    }
    __syncthreads();

    if (t < 32) {
        int c = t >> 4, o = t & 15;
        float se = sfin[c*17];
        float s = sfin[c*17 + 1 + o] / se;
        float s2 = s*s;
        #pragma unroll
        for (int off = 8; off > 0; off >>= 1)
            s2 += __shfl_xor_sync(0xffffffffu, s2, off, 16);
        float scale = (s2 / (1.f + s2)) / sqrtf(s2 + 1e-8f);
        float vv = scale * s;
        int cls = 2*cp + c;
        g_v[(b*NCLS + cls)*OD + o] = vv;
        if (!last) g_vc[(b*NCLS + cls)*OD + o] += vv;
    }
}

// ---------------- head ----------------
__global__ void head_kernel(float* __restrict__ out)
{
    int b = blockIdx.x;
    int t = threadIdx.x;
    __shared__ float len[NCLS];
    if (t < NCLS) {
        float s = 0.f;
        #pragma unroll
        for (int o = 0; o < OD; o++) {
            float x = g_v[(b*NCLS + t)*OD + o];
            s = fmaf(x, x, s);
        }
        len[t] = sqrtf(s);
    }
    __syncthreads();
    if (t == 0) {
        int best = 0; float bv = len[0];
        #pragma unroll
        for (int c = 1; c < NCLS; c++)
            if (len[c] > bv) { bv = len[c]; best = c; }
        g_cls[b] = best;
    }
    __syncthreads();
    int best = g_cls[b];
    if (t < NCLS) {
        out[OUT_OHE_OFF + b*NCLS + t] = (t == best) ? 1.0f : 0.0f;
        out[OUT_LEN_OFF + b*NCLS + t] = len[t];
    }
}

// ---------------- decoder ----------------
__global__ void dec1_kernel(const float* __restrict__ w1, const float* __restrict__ b1)
{
    int idx = blockIdx.x*256 + threadIdx.x;
    if (idx >= BATCH*512) return;
    int j = idx % 512, b = idx / 512;
    int cls = g_cls[b];
    const float* v = &g_v[(b*NCLS + cls)*OD];
    float a = b1[j];
    #pragma unroll
    for (int d = 0; d < OD; d++)
        a = fmaf(v[d], w1[(size_t)(cls*OD + d)*512 + j], a);
    g_h1[idx] = fmaxf(a, 0.f);
}

__global__ void dec2_kernel(const float* __restrict__ w2, const float* __restrict__ b2)
{
    int idx = blockIdx.x*256 + threadIdx.x;
    if (idx >= BATCH*1024) return;
    int j = idx % 1024, b = idx / 1024;
    const float* h = &g_h1[b*512];
    float a = b2[j];
    #pragma unroll 4
    for (int k = 0; k < 512; k++)
        a = fmaf(h[k], w2[(size_t)k*1024 + j], a);
    g_h2[idx] = fmaxf(a, 0.f);
}

__global__ void dec3_kernel(const float* __restrict__ w3, const float* __restrict__ b3,
                            float* __restrict__ out)
{
    int idx = blockIdx.x*256 + threadIdx.x;
    if (idx >= BATCH*784) return;
    int p = idx % 784, b = idx / 784;
    const float* h = &g_h2[b*1024];
    float a = b3[p];
    #pragma unroll 4
    for (int k = 0; k < 1024; k++)
        a = fmaf(h[k], w3[(size_t)k*784 + p], a);
    out[OUT_REC_OFF + idx] = 1.f / (1.f + expf(-a));
}

// ---------------- launch ----------------
extern "C" void kernel_launch(void* const* d_in, const int* in_sizes, int n_in,
                              void* d_out, int out_size)
{
    const float* imgs    = (const float*)d_in[0];
    const float* conv1_w = (const float*)d_in[1];
    const float* conv1_b = (const float*)d_in[2];
    const float* conv2_w = (const float*)d_in[3];
    const float* conv2_b = (const float*)d_in[4];
    const float* W_digit = (const float*)d_in[5];
    const float* dec_w1  = (const float*)d_in[6];
    const float* dec_b1  = (const float*)d_in[7];
    const float* dec_w2  = (const float*)d_in[8];
    const float* dec_b2  = (const float*)d_in[9];
    const float* dec_w3  = (const float*)d_in[10];
    const float* dec_b3  = (const float*)d_in[11];
    float* out = (float*)d_out;

    cudaFuncSetAttribute(conv2_tc_kernel,
                         cudaFuncAttributeMaxDynamicSharedMemorySize, CONV2_SMEM);

    wsplit_kernel<<<dim3(8, 8), 256>>>(conv2_w);
    conv1_kernel<<<dim3(C1, BATCH), 256>>>(imgs, conv1_w, conv1_b);
    xpose_kernel<<<BATCH, 512>>>();
    conv2_tc_kernel<<<MTILES, 512, CONV2_SMEM>>>(conv2_b);
    squash_prim_kernel<<<(BATCH*NCAP + 255)/256, 256>>>();
    uhat16_kernel<<<NCAP/4, 640>>>(W_digit);
    vc_zero_kernel<<<(BATCH*NCLS*OD + 255)/256, 256>>>();
    for (int it = 0; it < 3; it++)
        route16_kernel<<<dim3(5, BATCH), 512>>>(it == 2 ? 1 : 0);
    head_kernel<<<BATCH, 32>>>(out);
    dec1_kernel<<<(BATCH*512 + 255)/256, 256>>>(dec_w1, dec_b1);
    dec2_kernel<<<(BATCH*1024 + 255)/256, 256>>>(dec_w2, dec_b2);
    dec3_kernel<<<(BATCH*784 + 255)/256, 256>>>(dec_w3, dec_b3, out);
    (void)in_sizes; (void)n_in; (void)out_size;
}

// round 10
// speedup vs baseline: 3.5099x; 1.3954x over previous
#include <cuda_runtime.h>
#include <cuda_bf16.h>
#include <cuda_fp16.h>
#include <math.h>
#include <stdint.h>

// ---------------- problem constants ----------------
#define BATCH 128
#define C1 256
#define H1 20
#define C2 256
#define H2 12
#define NMAP 32
#define NPRIM 144
#define NCAP (NMAP*NPRIM)   // 4608
#define NCLS 10
#define OD 16
#define ID 8

#define OUT_OHE_OFF 0
#define OUT_REC_OFF (BATCH*NCLS)
#define OUT_LEN_OFF (BATCH*NCLS + BATCH*784)

// conv2 GEMM geometry (K reordered: k' = (ky*9+kx)*256 + ic)
#define KTOT 20736
#define KC   64
#define NBLK 324
#define MTILES 144

// ---------------- device scratch ----------------
__device__ float g_conv1[(size_t)BATCH*C1*400];
// X packed: [b][px][seg0..3][hi 64 bf16 | lo 64 bf16]  (256B per (px,seg))
__device__ __nv_bfloat16 g_x[(size_t)BATCH*400*4*128];
// W pre-swizzled per 64KB chunk blocks (smem image, both planes)
__device__ __nv_bfloat16 g_wsw[(size_t)NBLK*65536/2];
__device__ float g_p[(size_t)BATCH*C2*NPRIM];
__device__ float g_u[(size_t)BATCH*NCAP*ID];
__device__ __half g_uh16[(size_t)BATCH*NCAP*NCLS*OD];  // 188MB fp16 u_hat
__device__ float g_v[BATCH*NCLS*OD];
__device__ float g_vc[BATCH*NCLS*OD];
__device__ int   g_cls[BATCH];
__device__ float g_h1[BATCH*512];
__device__ float g_h2[BATCH*1024];

// ---------------- small PTX helpers ----------------
__device__ __forceinline__ uint32_t smem_u32(const void* p) {
    uint32_t a;
    asm("{ .reg .u64 t; cvta.to.shared.u64 t, %1; cvt.u32.u64 %0, t; }"
        : "=r"(a) : "l"(p));
    return a;
}
__device__ __forceinline__ void ldsm4(uint32_t* r, uint32_t a) {
    asm volatile("ldmatrix.sync.aligned.m8n8.x4.shared.b16 {%0,%1,%2,%3}, [%4];"
        : "=r"(r[0]), "=r"(r[1]), "=r"(r[2]), "=r"(r[3]) : "r"(a));
}
__device__ __forceinline__ void ldsm4t(uint32_t* r, uint32_t a) {
    asm volatile("ldmatrix.sync.aligned.m8n8.x4.trans.shared.b16 {%0,%1,%2,%3}, [%4];"
        : "=r"(r[0]), "=r"(r[1]), "=r"(r[2]), "=r"(r[3]) : "r"(a));
}
__device__ __forceinline__ void mma_bf16(float* c, const uint32_t* a, const uint32_t* b) {
    asm volatile("mma.sync.aligned.m16n8k16.row.col.f32.bf16.bf16.f32 "
        "{%0,%1,%2,%3}, {%4,%5,%6,%7}, {%8,%9}, {%0,%1,%2,%3};"
        : "+f"(c[0]), "+f"(c[1]), "+f"(c[2]), "+f"(c[3])
        : "r"(a[0]), "r"(a[1]), "r"(a[2]), "r"(a[3]), "r"(b[0]), "r"(b[1]));
}
__device__ __forceinline__ void mbar_init(uint32_t mbar, uint32_t cnt) {
    asm volatile("mbarrier.init.shared.b64 [%0], %1;" :: "r"(mbar), "r"(cnt) : "memory");
}
__device__ __forceinline__ void mbar_expect(uint32_t mbar, uint32_t bytes) {
    asm volatile("mbarrier.arrive.expect_tx.shared.b64 _, [%0], %1;"
                 :: "r"(mbar), "r"(bytes) : "memory");
}
__device__ __forceinline__ void bulkcp(uint32_t dst, const void* src, uint32_t size,
                                       uint32_t mbar) {
    asm volatile(
        "cp.async.bulk.shared::cluster.global.mbarrier::complete_tx::bytes [%0], [%1], %2, [%3];"
        :: "r"(dst), "l"(src), "r"(size), "r"(mbar) : "memory");
}
__device__ __forceinline__ void mbar_wait(uint32_t mbar, uint32_t parity) {
    uint32_t done;
    asm volatile("{\n\t.reg .pred p;\n\t"
        "mbarrier.try_wait.parity.acquire.cta.shared::cta.b64 p, [%1], %2;\n\t"
        "selp.b32 %0, 1, 0, p;\n\t}" : "=r"(done) : "r"(mbar), "r"(parity) : "memory");
    while (!done) {
        asm volatile("{\n\t.reg .pred p;\n\t"
            "mbarrier.try_wait.parity.acquire.cta.shared::cta.b64 p, [%1], %2, 0x989680;\n\t"
            "selp.b32 %0, 1, 0, p;\n\t}" : "=r"(done) : "r"(mbar), "r"(parity) : "memory");
    }
}
__device__ __forceinline__ void fence_async_smem() {
    asm volatile("fence.proxy.async.shared::cta;" ::: "memory");
}

// smem layout per buffer: X rows (272B stride, 128 rows) then W (64KB swizzled image)
#define OFF_X  0u
#define OFF_W  34816u     // 128*272, already 1024-aligned
#define BUFB   100352u    // 34816 + 65536
#define CONV2_SMEM (1024u + 2u*BUFB)   // 201728

// ---------------- conv1 + relu ----------------
__global__ __launch_bounds__(256) void conv1_kernel(
    const float* __restrict__ img, const float* __restrict__ w,
    const float* __restrict__ bias)
{
    int oc = blockIdx.x, b = blockIdx.y;
    __shared__ float si[28*28];
    __shared__ float sw[81];
    int t = threadIdx.x;
    for (int i = t; i < 784; i += 256) si[i] = img[b*784 + i];
    if (t < 81) sw[t] = w[oc*81 + t];
    __syncthreads();
    float bs = bias[oc];
    for (int p = t; p < 400; p += 256) {
        int oy = p / 20, ox = p % 20;
        float a = 0.f;
        #pragma unroll
        for (int ky = 0; ky < 9; ky++)
            #pragma unroll
            for (int kx = 0; kx < 9; kx++)
                a = fmaf(sw[ky*9+kx], si[(oy+ky)*28 + ox + kx], a);
        a += bs;
        g_conv1[((size_t)(b*C1 + oc))*400 + oy*20 + ox] = fmaxf(a, 0.f);
    }
}

// ---------------- conv1 NCHW fp32 -> packed hi/lo bf16 [b][px][seg][hi64|lo64] ----------------
__global__ __launch_bounds__(512) void xpose_kernel()
{
    __shared__ uint32_t s[400*17];
    int b = blockIdx.x;
    int t = threadIdx.x;
    for (int c0 = 0; c0 < 256; c0 += 16) {
        __syncthreads();
        for (int i = t; i < 16*400; i += 512) {
            int c = i / 400, px = i - c*400;
            float v = g_conv1[((size_t)(b*C1 + c0 + c))*400 + px];
            __nv_bfloat16 h = __float2bfloat16(v);
            __nv_bfloat16 l = __float2bfloat16(v - __bfloat162float(h));
            uint32_t pk = (uint32_t)__bfloat16_as_ushort(h)
                        | ((uint32_t)__bfloat16_as_ushort(l) << 16);
            s[px*17 + c] = pk;
        }
        __syncthreads();
        for (int i = t; i < 400*16; i += 512) {
            int px = i >> 4, cl = i & 15;
            int c = c0 + cl;
            int seg = c >> 6, icl = c & 63;
            uint32_t pk = s[px*17 + cl];
            size_t base = (((size_t)b*400 + px)*4 + seg)*128;
            g_x[base + icl]      = __ushort_as_bfloat16((unsigned short)(pk & 0xFFFFu));
            g_x[base + 64 + icl] = __ushort_as_bfloat16((unsigned short)(pk >> 16));
        }
    }
}

// ---------------- W transpose+split into pre-swizzled 64KB chunk blocks ----------------
__global__ __launch_bounds__(256) void wsplit_kernel(const float* __restrict__ w2)
{
    __shared__ float s[8][32][33];
    int ic0 = blockIdx.x * 32, oc0 = blockIdx.y * 32;
    int t = threadIdx.x;
    for (int rc = 0; rc < 81; rc += 8) {
        int rcnt = min(8, 81 - rc);
        __syncthreads();
        #pragma unroll
        for (int pp = 0; pp < 4; pp++) {
            int pair = t + pp*256;
            int icl = pair & 31, ocl = pair >> 5;
            const float* src = w2 + (size_t)(oc0+ocl)*KTOT + (size_t)(ic0+icl)*81 + rc;
            for (int rr = 0; rr < rcnt; rr++)
                s[rr][icl][ocl] = src[rr];
        }
        __syncthreads();
        for (int rr = 0; rr < rcnt; rr++) {
            #pragma unroll
            for (int pp = 0; pp < 4; pp++) {
                int pair = t + pp*256;
                int ocl = pair & 31, icl = pair >> 5;
                float v = s[rr][icl][ocl];
                __nv_bfloat16 h = __float2bfloat16(v);
                __nv_bfloat16 l = __float2bfloat16(v - __bfloat162float(h));
                int k = (rc+rr)*256 + ic0 + icl;
                int kb = k >> 6, krow = k & 63;
                int oc = oc0 + ocl;
                size_t byte = (size_t)kb*65536 + (size_t)krow*512
                            + (uint32_t)((oc*2) ^ ((krow & 7) << 4));
                g_wsw[byte >> 1]             = h;
                g_wsw[(byte + 32768) >> 1]   = l;
            }
        }
    }
}

// ---------------- conv2 tensor-core kernel (bulk-copy staging) ----------------
__global__ void __launch_bounds__(512, 1) conv2_tc_kernel(const float* __restrict__ b2)
{
    extern __shared__ char smem[];
    uint32_t sbase = smem_u32(smem);
    int t = threadIdx.x;
    int warp = t >> 5, lane = t & 31;
    int tile = blockIdx.x;

    int warp_m = warp >> 2;        // 0..3
    int warp_n = warp & 3;         // 0..3

    // producer row mapping (threads 0..127 stage X row t; thread 128 stages W)
    int trow = (t < 128) ? t : 0;
    int grow = tile*128 + trow;
    int bimg = grow / NPRIM;
    int posl = grow - bimg*NPRIM;
    int oy = posl / 12, ox = posl - (posl/12)*12;
    int xb400 = bimg*400;

    uint32_t mbar0 = sbase, mbar1 = sbase + 8;

    if (t == 0) { mbar_init(mbar0, 129); mbar_init(mbar1, 129); fence_async_smem(); }
    __syncthreads();

    float acc[2][8][4];
    #pragma unroll
    for (int mt = 0; mt < 2; mt++)
        #pragma unroll
        for (int nt = 0; nt < 8; nt++)
            #pragma unroll
            for (int e = 0; e < 4; e++) acc[mt][nt][e] = 0.f;

    // stage chunk kn into buffer buf (smem addr), barrier mbar
    auto stage = [&](int kn, uint32_t buf, uint32_t mbar) {
        if (t < 128) {
            int r = kn >> 2, seg = kn & 3;
            int ky = r / 9, kx = r - ky*9;
            const char* src = (const char*)g_x
                + ((((size_t)(xb400 + (oy+ky)*20 + ox + kx))*4 + seg) << 8);
            mbar_expect(mbar, 256);
            bulkcp(buf + OFF_X + (uint32_t)t*272u, src, 256, mbar);
        } else if (t == 128) {
            mbar_expect(mbar, 65536);
            bulkcp(buf + OFF_W, (const char*)g_wsw + (size_t)kn*65536, 65536, mbar);
        }
    };

    uint32_t buf0 = sbase + 1024u, buf1 = sbase + 1024u + BUFB;
    stage(0, buf0, mbar0);

    int ph0 = 0, ph1 = 0;
    for (int kb = 0; kb < NBLK; kb++) {
        int cur = kb & 1;
        uint32_t curbuf = cur ? buf1 : buf0;
        if (kb + 1 < NBLK)
            stage(kb + 1, cur ? buf0 : buf1, cur ? mbar0 : mbar1);

        if (cur) { mbar_wait(mbar1, ph1); }
        else     { mbar_wait(mbar0, ph0); }

        // ---- compute chunk kb (B path identical to proven R8 core) ----
        #pragma unroll
        for (int kk = 0; kk < 4; kk++) {
            uint32_t bh[8][2], bl[8][2];
            #pragma unroll
            for (int np = 0; np < 4; np++) {
                int j = lane >> 3, rw = lane & 7;
                int krow = kk*16 + (j & 1)*8 + rw;
                int ncol = warp_n*64 + np*16 + (j >> 1)*8;
                uint32_t byte = (uint32_t)(krow*512 + ((ncol*2) ^ ((krow & 7) << 4)));
                uint32_t r[4];
                ldsm4t(r, curbuf + OFF_W + byte);
                bh[2*np][0] = r[0]; bh[2*np][1] = r[1];
                bh[2*np+1][0] = r[2]; bh[2*np+1][1] = r[3];
                ldsm4t(r, curbuf + OFF_W + 32768u + byte);
                bl[2*np][0] = r[0]; bl[2*np][1] = r[1];
                bl[2*np+1][0] = r[2]; bl[2*np+1][1] = r[3];
            }
            #pragma unroll
            for (int mt = 0; mt < 2; mt++) {
                int rowl = warp_m*32 + mt*16 + (lane & 15);
                uint32_t abase = curbuf + OFF_X + (uint32_t)rowl*272u
                               + (uint32_t)((kk*16 + (lane >> 4)*8)*2);
                uint32_t ah[4], al[4];
                ldsm4(ah, abase);
                ldsm4(al, abase + 128u);
                #pragma unroll
                for (int nt = 0; nt < 8; nt++) {
                    mma_bf16(acc[mt][nt], ah, bh[nt]);
                    mma_bf16(acc[mt][nt], ah, bl[nt]);
                    mma_bf16(acc[mt][nt], al, bh[nt]);
                }
            }
        }
        if (cur) ph1 ^= 1; else ph0 ^= 1;
        __syncthreads();
    }

    // ---- epilogue: write D + bias to g_p ----
    #pragma unroll
    for (int mt = 0; mt < 2; mt++) {
        int pr0 = tile*128 + warp_m*32 + mt*16 + (lane >> 2);
        #pragma unroll
        for (int half = 0; half < 2; half++) {
            int pr = pr0 + half*8;
            int b = pr / NPRIM;
            int pl = pr - b*NPRIM;
            #pragma unroll
            for (int nt = 0; nt < 8; nt++) {
                int oc = warp_n*64 + nt*8 + (lane & 3)*2;
                float c0 = acc[mt][nt][half*2 + 0];
                float c1 = acc[mt][nt][half*2 + 1];
                g_p[((size_t)b*C2 + oc)*NPRIM + pl]     = c0 + __ldg(&b2[oc]);
                g_p[((size_t)b*C2 + oc + 1)*NPRIM + pl] = c1 + __ldg(&b2[oc+1]);
            }
        }
    }
}

// ---------------- primary capsule squash ----------------
__global__ void squash_prim_kernel()
{
    int idx = blockIdx.x*blockDim.x + threadIdx.x;
    if (idx >= BATCH*NCAP) return;
    int pos = idx % NPRIM;
    int m   = (idx / NPRIM) % NMAP;
    int b   = idx / NCAP;
    float x[ID]; float s2 = 0.f;
    #pragma unroll
    for (int d = 0; d < ID; d++) {
        x[d] = g_p[(((size_t)b*C2 + d*NMAP + m)*NPRIM) + pos];
        s2 = fmaf(x[d], x[d], s2);
    }
    float scale = (s2 / (1.f + s2)) / sqrtf(s2 + 1e-8f);
    float* up = g_u + (size_t)idx*ID;
    #pragma unroll
    for (int d = 0; d < ID; d++) up[d] = scale * x[d];
}

// ---------------- u_hat materialization (fp16) ----------------
__global__ __launch_bounds__(640) void uhat16_kernel(const float* __restrict__ Wd)
{
    int t = threadIdx.x;
    int co = t % 160, nl = t / 160;
    int n = blockIdx.x*4 + nl;
    const float4* wr = (const float4*)(Wd + ((size_t)n*160 + co)*8);
    float4 w0 = wr[0], w1 = wr[1];
    __half* outp = g_uh16 + (size_t)n*160 + co;
    const float4* up = (const float4*)(g_u + (size_t)n*8);
    #pragma unroll 4
    for (int b = 0; b < BATCH; b++) {
        float4 ua = __ldg(up), ub = __ldg(up + 1);
        float a = w0.x*ua.x;
        a = fmaf(w0.y, ua.y, a); a = fmaf(w0.z, ua.z, a); a = fmaf(w0.w, ua.w, a);
        a = fmaf(w1.x, ub.x, a); a = fmaf(w1.y, ub.y, a);
        a = fmaf(w1.z, ub.z, a); a = fmaf(w1.w, ub.w, a);
        outp[(size_t)b*NCAP*160] = __float2half_rn(a);
        up += NCAP*8/4;
    }
}

// ---------------- routing from materialized fp16 u_hat ----------------
__global__ void vc_zero_kernel()
{
    int idx = blockIdx.x*256 + threadIdx.x;
    if (idx < BATCH*NCLS*OD) g_vc[idx] = 0.f;
}

__device__ __forceinline__ void unpack8(const uint4& q, float* f) {
    const __half2* h = (const __half2*)&q;
    #pragma unroll
    for (int j = 0; j < 4; j++) {
        float2 v = __half22float2(h[j]);
        f[2*j] = v.x; f[2*j+1] = v.y;
    }
}

__global__ __launch_bounds__(512) void route16_kernel(int last)
{
    int cp = blockIdx.x;
    int b  = blockIdx.y;
    int t  = threadIdx.x;
    __shared__ float sVc[32];
    __shared__ float sred[16][34];
    __shared__ float sfin[34];

    if (t < 32) sVc[t] = g_vc[(b*NCLS + 2*cp + (t >> 4))*OD + (t & 15)];
    __syncthreads();
    float Vc0[16], Vc1[16];
    #pragma unroll
    for (int o = 0; o < 16; o++) { Vc0[o] = sVc[o]; Vc1[o] = sVc[16+o]; }

    float se0 = 0.f, se1 = 0.f;
    float sv0[16], sv1[16];
    #pragma unroll
    for (int o = 0; o < 16; o++) { sv0[o] = 0.f; sv1[o] = 0.f; }

    #pragma unroll 1
    for (int j = 0; j < 9; j++) {
        int n = t + j*512;
        const uint4* up = (const uint4*)(g_uh16 + ((size_t)b*NCAP + n)*160 + cp*32);
        uint4 q0 = up[0], q1 = up[1], q2 = up[2], q3 = up[3];
        float uh0[16], uh1[16];
        unpack8(q0, uh0); unpack8(q1, uh0+8);
        unpack8(q2, uh1); unpack8(q3, uh1+8);
        float b0 = 0.f, b1 = 0.f;
        #pragma unroll
        for (int o = 0; o < 16; o++) {
            b0 = fmaf(uh0[o], Vc0[o], b0);
            b1 = fmaf(uh1[o], Vc1[o], b1);
        }
        float e0 = __expf(b0), e1 = __expf(b1);
        se0 += e0; se1 += e1;
        #pragma unroll
        for (int o = 0; o < 16; o++) {
            sv0[o] = fmaf(e0, uh0[o], sv0[o]);
            sv1[o] = fmaf(e1, uh1[o], sv1[o]);
        }
    }

    #pragma unroll
    for (int off = 16; off > 0; off >>= 1) {
        se0 += __shfl_down_sync(0xffffffffu, se0, off);
        se1 += __shfl_down_sync(0xffffffffu, se1, off);
        #pragma unroll
        for (int o = 0; o < 16; o++) {
            sv0[o] += __shfl_down_sync(0xffffffffu, sv0[o], off);
            sv1[o] += __shfl_down_sync(0xffffffffu, sv1[o], off);
        }
    }
    int wid = t >> 5, lane = t & 31;
    if (lane == 0) {
        sred[wid][0] = se0;
        sred[wid][17] = se1;
        #pragma unroll
        for (int o = 0; o < 16; o++) {
            sred[wid][1+o] = sv0[o];
            sred[wid][18+o] = sv1[o];
        }
    }
    __syncthreads();

    if (t < 34) {
        float tot = 0.f;
        #pragma unroll
        for (int w = 0; w < 16; w++) tot += sred[w][t];
        sfin[t] = tot;
    }
    __syncthreads();

    if (t < 32) {
        int c = t >> 4, o = t & 15;
        float se = sfin[c*17];
        float s = sfin[c*17 + 1 + o] / se;
        float s2 = s*s;
        #pragma unroll
        for (int off = 8; off > 0; off >>= 1)
            s2 += __shfl_xor_sync(0xffffffffu, s2, off, 16);
        float scale = (s2 / (1.f + s2)) / sqrtf(s2 + 1e-8f);
        float vv = scale * s;
        int cls = 2*cp + c;
        g_v[(b*NCLS + cls)*OD + o] = vv;
        if (!last) g_vc[(b*NCLS + cls)*OD + o] += vv;
    }
}

// ---------------- head ----------------
__global__ void head_kernel(float* __restrict__ out)
{
    int b = blockIdx.x;
    int t = threadIdx.x;
    __shared__ float len[NCLS];
    if (t < NCLS) {
        float s = 0.f;
        #pragma unroll
        for (int o = 0; o < OD; o++) {
            float x = g_v[(b*NCLS + t)*OD + o];
            s = fmaf(x, x, s);
        }
        len[t] = sqrtf(s);
    }
    __syncthreads();
    if (t == 0) {
        int best = 0; float bv = len[0];
        #pragma unroll
        for (int c = 1; c < NCLS; c++)
            if (len[c] > bv) { bv = len[c]; best = c; }
        g_cls[b] = best;
    }
    __syncthreads();
    int best = g_cls[b];
    if (t < NCLS) {
        out[OUT_OHE_OFF + b*NCLS + t] = (t == best) ? 1.0f : 0.0f;
        out[OUT_LEN_OFF + b*NCLS + t] = len[t];
    }
}

// ---------------- decoder ----------------
__global__ void dec1_kernel(const float* __restrict__ w1, const float* __restrict__ b1)
{
    int idx = blockIdx.x*256 + threadIdx.x;
    if (idx >= BATCH*512) return;
    int j = idx % 512, b = idx / 512;
    int cls = g_cls[b];
    const float* v = &g_v[(b*NCLS + cls)*OD];
    float a = b1[j];
    #pragma unroll
    for (int d = 0; d < OD; d++)
        a = fmaf(v[d], w1[(size_t)(cls*OD + d)*512 + j], a);
    g_h1[idx] = fmaxf(a, 0.f);
}

__global__ void dec2_kernel(const float* __restrict__ w2, const float* __restrict__ b2)
{
    int idx = blockIdx.x*256 + threadIdx.x;
    if (idx >= BATCH*1024) return;
    int j = idx % 1024, b = idx / 1024;
    const float* h = &g_h1[b*512];
    float a = b2[j];
    #pragma unroll 4
    for (int k = 0; k < 512; k++)
        a = fmaf(h[k], w2[(size_t)k*1024 + j], a);
    g_h2[idx] = fmaxf(a, 0.f);
}

__global__ void dec3_kernel(const float* __restrict__ w3, const float* __restrict__ b3,
                            float* __restrict__ out)
{
    int idx = blockIdx.x*256 + threadIdx.x;
    if (idx >= BATCH*784) return;
    int p = idx % 784, b = idx / 784;
    const float* h = &g_h2[b*1024];
    float a = b3[p];
    #pragma unroll 4
    for (int k = 0; k < 1024; k++)
        a = fmaf(h[k], w3[(size_t)k*784 + p], a);
    out[OUT_REC_OFF + idx] = 1.f / (1.f + expf(-a));
}

// ---------------- launch ----------------
extern "C" void kernel_launch(void* const* d_in, const int* in_sizes, int n_in,
                              void* d_out, int out_size)
{
    const float* imgs    = (const float*)d_in[0];
    const float* conv1_w = (const float*)d_in[1];
    const float* conv1_b = (const float*)d_in[2];
    const float* conv2_w = (const float*)d_in[3];
    const float* conv2_b = (const float*)d_in[4];
    const float* W_digit = (const float*)d_in[5];
    const float* dec_w1  = (const float*)d_in[6];
    const float* dec_b1  = (const float*)d_in[7];
    const float* dec_w2  = (const float*)d_in[8];
    const float* dec_b2  = (const float*)d_in[9];
    const float* dec_w3  = (const float*)d_in[10];
    const float* dec_b3  = (const float*)d_in[11];
    float* out = (float*)d_out;

    cudaFuncSetAttribute(conv2_tc_kernel,
                         cudaFuncAttributeMaxDynamicSharedMemorySize, CONV2_SMEM);

    wsplit_kernel<<<dim3(8, 8), 256>>>(conv2_w);
    conv1_kernel<<<dim3(C1, BATCH), 256>>>(imgs, conv1_w, conv1_b);
    xpose_kernel<<<BATCH, 512>>>();
    conv2_tc_kernel<<<MTILES, 512, CONV2_SMEM>>>(conv2_b);
    squash_prim_kernel<<<(BATCH*NCAP + 255)/256, 256>>>();
    uhat16_kernel<<<NCAP/4, 640>>>(W_digit);
    vc_zero_kernel<<<(BATCH*NCLS*OD + 255)/256, 256>>>();
    for (int it = 0; it < 3; it++)
        route16_kernel<<<dim3(5, BATCH), 512>>>(it == 2 ? 1 : 0);
    head_kernel<<<BATCH, 32>>>(out);
    dec1_kernel<<<(BATCH*512 + 255)/256, 256>>>(dec_w1, dec_b1);
    dec2_kernel<<<(BATCH*1024 + 255)/256, 256>>>(dec_w2, dec_b2);
    dec3_kernel<<<(BATCH*784 + 255)/256, 256>>>(dec_w3, dec_b3, out);
    (void)in_sizes; (void)n_in; (void)out_size;
}

// round 13
// speedup vs baseline: 3.6218x; 1.0319x over previous
#include <cuda_runtime.h>
#include <cuda_bf16.h>
#include <cuda_fp16.h>
#include <math.h>
#include <stdint.h>

// ---------------- problem constants ----------------
#define BATCH 128
#define C1 256
#define H1 20
#define C2 256
#define H2 12
#define NMAP 32
#define NPRIM 144
#define NCAP (NMAP*NPRIM)   // 4608
#define NCLS 10
#define OD 16
#define ID 8

#define OUT_OHE_OFF 0
#define OUT_REC_OFF (BATCH*NCLS)
#define OUT_LEN_OFF (BATCH*NCLS + BATCH*784)

// conv2 GEMM geometry (K reordered: k' = (ky*9+kx)*256 + ic)
#define KTOT 20736
#define KC   64
#define NBLK 324
#define MTILES 144

// ---------------- device scratch ----------------
__device__ float g_conv1[(size_t)BATCH*C1*400];
// X packed: [b][px][seg0..3][hi 64 bf16 | lo 64 bf16]  (256B per (px,seg))
__device__ __nv_bfloat16 g_x[(size_t)BATCH*400*4*128];
// W pre-swizzled per 64KB chunk blocks (smem image, both planes)
__device__ __nv_bfloat16 g_wsw[(size_t)NBLK*65536/2];
__device__ float g_u[(size_t)BATCH*NCAP*ID];
__device__ __half g_uh16[(size_t)BATCH*NCAP*NCLS*OD];  // 188MB fp16 u_hat
__device__ float g_v[BATCH*NCLS*OD];
__device__ float g_vc[BATCH*NCLS*OD];
__device__ int   g_cls[BATCH];
__device__ float g_h1[BATCH*512];
__device__ float g_h2[BATCH*1024];

// ---------------- small PTX helpers ----------------
__device__ __forceinline__ uint32_t smem_u32(const void* p) {
    uint32_t a;
    asm("{ .reg .u64 t; cvta.to.shared.u64 t, %1; cvt.u32.u64 %0, t; }"
        : "=r"(a) : "l"(p));
    return a;
}
__device__ __forceinline__ void ldsm4(uint32_t* r, uint32_t a) {
    asm volatile("ldmatrix.sync.aligned.m8n8.x4.shared.b16 {%0,%1,%2,%3}, [%4];"
        : "=r"(r[0]), "=r"(r[1]), "=r"(r[2]), "=r"(r[3]) : "r"(a));
}
__device__ __forceinline__ void ldsm4t(uint32_t* r, uint32_t a) {
    asm volatile("ldmatrix.sync.aligned.m8n8.x4.trans.shared.b16 {%0,%1,%2,%3}, [%4];"
        : "=r"(r[0]), "=r"(r[1]), "=r"(r[2]), "=r"(r[3]) : "r"(a));
}
__device__ __forceinline__ void mma_bf16(float* c, const uint32_t* a, const uint32_t* b) {
    asm volatile("mma.sync.aligned.m16n8k16.row.col.f32.bf16.bf16.f32 "
        "{%0,%1,%2,%3}, {%4,%5,%6,%7}, {%8,%9}, {%0,%1,%2,%3};"
        : "+f"(c[0]), "+f"(c[1]), "+f"(c[2]), "+f"(c[3])
        : "r"(a[0]), "r"(a[1]), "r"(a[2]), "r"(a[3]), "r"(b[0]), "r"(b[1]));
}
__device__ __forceinline__ void mbar_init(uint32_t mbar, uint32_t cnt) {
    asm volatile("mbarrier.init.shared.b64 [%0], %1;" :: "r"(mbar), "r"(cnt) : "memory");
}
__device__ __forceinline__ void mbar_expect(uint32_t mbar, uint32_t bytes) {
    asm volatile("mbarrier.arrive.expect_tx.shared.b64 _, [%0], %1;"
                 :: "r"(mbar), "r"(bytes) : "memory");
}
__device__ __forceinline__ void bulkcp(uint32_t dst, const void* src, uint32_t size,
                                       uint32_t mbar) {
    asm volatile(
        "cp.async.bulk.shared::cluster.global.mbarrier::complete_tx::bytes [%0], [%1], %2, [%3];"
        :: "r"(dst), "l"(src), "r"(size), "r"(mbar) : "memory");
}
__device__ __forceinline__ void mbar_wait(uint32_t mbar, uint32_t parity) {
    uint32_t done;
    asm volatile("{\n\t.reg .pred p;\n\t"
        "mbarrier.try_wait.parity.acquire.cta.shared::cta.b64 p, [%1], %2;\n\t"
        "selp.b32 %0, 1, 0, p;\n\t}" : "=r"(done) : "r"(mbar), "r"(parity) : "memory");
    while (!done) {
        asm volatile("{\n\t.reg .pred p;\n\t"
            "mbarrier.try_wait.parity.acquire.cta.shared::cta.b64 p, [%1], %2, 0x989680;\n\t"
            "selp.b32 %0, 1, 0, p;\n\t}" : "=r"(done) : "r"(mbar), "r"(parity) : "memory");
    }
}
__device__ __forceinline__ void fence_async_smem() {
    asm volatile("fence.proxy.async.shared::cta;" ::: "memory");
}

// smem layout per buffer: X rows (272B stride, 128 rows) then W (64KB swizzled image)
#define OFF_X  0u
#define OFF_W  34816u     // 128*272, already 1024-aligned
#define BUFB   100352u    // 34816 + 65536
#define CONV2_SMEM (1024u + 2u*BUFB)   // 201728

// ---------------- conv1 + relu ----------------
__global__ __launch_bounds__(256) void conv1_kernel(
    const float* __restrict__ img, const float* __restrict__ w,
    const float* __restrict__ bias)
{
    int oc = blockIdx.x, b = blockIdx.y;
    __shared__ float si[28*28];
    __shared__ float sw[81];
    int t = threadIdx.x;
    for (int i = t; i < 784; i += 256) si[i] = img[b*784 + i];
    if (t < 81) sw[t] = w[oc*81 + t];
    __syncthreads();
    float bs = bias[oc];
    for (int p = t; p < 400; p += 256) {
        int oy = p / 20, ox = p % 20;
        float a = 0.f;
        #pragma unroll
        for (int ky = 0; ky < 9; ky++)
            #pragma unroll
            for (int kx = 0; kx < 9; kx++)
                a = fmaf(sw[ky*9+kx], si[(oy+ky)*28 + ox + kx], a);
        a += bs;
        g_conv1[((size_t)(b*C1 + oc))*400 + oy*20 + ox] = fmaxf(a, 0.f);
    }
}

// ---------------- conv1 NCHW fp32 -> packed hi/lo bf16 [b][px][seg][hi64|lo64] ----------------
__global__ __launch_bounds__(512) void xpose_kernel()
{
    __shared__ uint32_t s[400*17];
    int b = blockIdx.x;
    int t = threadIdx.x;
    for (int c0 = 0; c0 < 256; c0 += 16) {
        __syncthreads();
        for (int i = t; i < 16*400; i += 512) {
            int c = i / 400, px = i - c*400;
            float v = g_conv1[((size_t)(b*C1 + c0 + c))*400 + px];
            __nv_bfloat16 h = __float2bfloat16(v);
            __nv_bfloat16 l = __float2bfloat16(v - __bfloat162float(h));
            uint32_t pk = (uint32_t)__bfloat16_as_ushort(h)
                        | ((uint32_t)__bfloat16_as_ushort(l) << 16);
            s[px*17 + c] = pk;
        }
        __syncthreads();
        for (int i = t; i < 400*16; i += 512) {
            int px = i >> 4, cl = i & 15;
            int c = c0 + cl;
            int seg = c >> 6, icl = c & 63;
            uint32_t pk = s[px*17 + cl];
            size_t base = (((size_t)b*400 + px)*4 + seg)*128;
            g_x[base + icl]      = __ushort_as_bfloat16((unsigned short)(pk & 0xFFFFu));
            g_x[base + 64 + icl] = __ushort_as_bfloat16((unsigned short)(pk >> 16));
        }
    }
}

// ---------------- W split v2: block per 64KB chunk, smem-staged coalesced output ----------------
__global__ __launch_bounds__(256) void wsplit_kernel(const float* __restrict__ w2)
{
    extern __shared__ char img[];      // 65536 bytes
    int kb = blockIdx.x;               // 0..323
    int r   = kb >> 2;
    int ic0 = (kb & 3) * 64;
    int t = threadIdx.x;               // = oc
    const float* src = w2 + (size_t)t*KTOT + (size_t)ic0*81 + r;
    #pragma unroll 4
    for (int icl = 0; icl < 64; icl++) {
        float v = src[icl*81];
        __nv_bfloat16 h = __float2bfloat16(v);
        __nv_bfloat16 l = __float2bfloat16(v - __bfloat162float(h));
        uint32_t byte = (uint32_t)(icl*512 + ((t*2) ^ ((icl & 7) << 4)));
        *(__nv_bfloat16*)(img + byte)         = h;
        *(__nv_bfloat16*)(img + byte + 32768) = l;
    }
    __syncthreads();
    const uint4* s4 = (const uint4*)img;
    uint4* d4 = (uint4*)((char*)g_wsw + (size_t)kb*65536);
    #pragma unroll
    for (int i = 0; i < 16; i++)
        d4[t + i*256] = s4[t + i*256];
}

// ---------------- conv2 tensor-core kernel (bulk staging + fused squash epilogue) ----------------
__global__ void __launch_bounds__(512, 1) conv2_tc_kernel(const float* __restrict__ b2)
{
    extern __shared__ char smem[];
    uint32_t sbase = smem_u32(smem);
    int t = threadIdx.x;
    int warp = t >> 5, lane = t & 31;
    int tile = blockIdx.x;

    int warp_m = warp >> 2;        // 0..3
    int warp_n = warp & 3;         // 0..3

    // producer row mapping (threads 0..127 stage X row t; thread 128 stages W)
    int trow = (t < 128) ? t : 0;
    int grow = tile*128 + trow;
    int bimg = grow / NPRIM;
    int posl = grow - bimg*NPRIM;
    int oy = posl / 12, ox = posl - (posl/12)*12;
    int xb400 = bimg*400;

    uint32_t mbar0 = sbase, mbar1 = sbase + 8;

    if (t == 0) { mbar_init(mbar0, 129); mbar_init(mbar1, 129); fence_async_smem(); }
    __syncthreads();

    float acc[2][8][4];
    #pragma unroll
    for (int mt = 0; mt < 2; mt++)
        #pragma unroll
        for (int nt = 0; nt < 8; nt++)
            #pragma unroll
            for (int e = 0; e < 4; e++) acc[mt][nt][e] = 0.f;

    auto stage = [&](int kn, uint32_t buf, uint32_t mbar) {
        if (t < 128) {
            int r = kn >> 2, seg = kn & 3;
            int ky = r / 9, kx = r - ky*9;
            const char* src = (const char*)g_x
                + ((((size_t)(xb400 + (oy+ky)*20 + ox + kx))*4 + seg) << 8);
            mbar_expect(mbar, 256);
            bulkcp(buf + OFF_X + (uint32_t)t*272u, src, 256, mbar);
        } else if (t == 128) {
            mbar_expect(mbar, 65536);
            bulkcp(buf + OFF_W, (const char*)g_wsw + (size_t)kn*65536, 65536, mbar);
        }
    };

    uint32_t buf0 = sbase + 1024u, buf1 = sbase + 1024u + BUFB;
    stage(0, buf0, mbar0);

    int ph0 = 0, ph1 = 0;
    for (int kb = 0; kb < NBLK; kb++) {
        int cur = kb & 1;
        uint32_t curbuf = cur ? buf1 : buf0;
        if (kb + 1 < NBLK)
            stage(kb + 1, cur ? buf0 : buf1, cur ? mbar0 : mbar1);

        if (cur) { mbar_wait(mbar1, ph1); }
        else     { mbar_wait(mbar0, ph0); }

        #pragma unroll
        for (int kk = 0; kk < 4; kk++) {
            uint32_t bh[8][2], bl[8][2];
            #pragma unroll
            for (int np = 0; np < 4; np++) {
                int j = lane >> 3, rw = lane & 7;
                int krow = kk*16 + (j & 1)*8 + rw;
                int ncol = warp_n*64 + np*16 + (j >> 1)*8;
                uint32_t byte = (uint32_t)(krow*512 + ((ncol*2) ^ ((krow & 7) << 4)));
                uint32_t r[4];
                ldsm4t(r, curbuf + OFF_W + byte);
                bh[2*np][0] = r[0]; bh[2*np][1] = r[1];
                bh[2*np+1][0] = r[2]; bh[2*np+1][1] = r[3];
                ldsm4t(r, curbuf + OFF_W + 32768u + byte);
                bl[2*np][0] = r[0]; bl[2*np][1] = r[1];
                bl[2*np+1][0] = r[2]; bl[2*np+1][1] = r[3];
            }
            #pragma unroll
            for (int mt = 0; mt < 2; mt++) {
                int rowl = warp_m*32 + mt*16 + (lane & 15);
                uint32_t abase = curbuf + OFF_X + (uint32_t)rowl*272u
                               + (uint32_t)((kk*16 + (lane >> 4)*8)*2);
                uint32_t ah[4], al[4];
                ldsm4(ah, abase);
                ldsm4(al, abase + 128u);
                #pragma unroll
                for (int nt = 0; nt < 8; nt++) {
                    mma_bf16(acc[mt][nt], ah, bh[nt]);
                    mma_bf16(acc[mt][nt], ah, bl[nt]);
                    mma_bf16(acc[mt][nt], al, bh[nt]);
                }
            }
        }
        if (cur) ph1 ^= 1; else ph0 ^= 1;
        __syncthreads();
    }

    // ---- fused epilogue: stage D in smem, squash, write g_u directly ----
    float* sD = (float*)(smem + 1024);     // [128 pos][stride 260]
    #pragma unroll
    for (int mt = 0; mt < 2; mt++) {
        int pr = warp_m*32 + mt*16 + (lane >> 2);
        #pragma unroll
        for (int half = 0; half < 2; half++) {
            int p2 = pr + half*8;
            #pragma unroll
            for (int nt = 0; nt < 8; nt++) {
                int oc = warp_n*64 + nt*8 + (lane & 3)*2;
                sD[p2*260 + oc]     = acc[mt][nt][half*2 + 0] + __ldg(&b2[oc]);
                sD[p2*260 + oc + 1] = acc[mt][nt][half*2 + 1] + __ldg(&b2[oc+1]);
            }
        }
    }
    __syncthreads();

    #pragma unroll 1
    for (int iter = 0; iter < 8; iter++) {
        int q = iter*512 + t;
        int pos = q & 127;
        int m   = q >> 7;
        int gq = tile*128 + pos;
        int b  = gq / NPRIM;
        int pl = gq - b*NPRIM;
        float x[8]; float s2 = 0.f;
        #pragma unroll
        for (int d = 0; d < 8; d++) {
            x[d] = sD[pos*260 + m + d*32];
            s2 = fmaf(x[d], x[d], s2);
        }
        float scale = (s2 / (1.f + s2)) / sqrtf(s2 + 1e-8f);
        float4* up = (float4*)(g_u + ((size_t)b*NCAP + m*NPRIM + pl)*8);
        up[0] = make_float4(scale*x[0], scale*x[1], scale*x[2], scale*x[3]);
        up[1] = make_float4(scale*x[4], scale*x[5], scale*x[6], scale*x[7]);
    }
}

// ---------------- u_hat materialization (fp16) ----------------
__global__ __launch_bounds__(640) void uhat16_kernel(const float* __restrict__ Wd)
{
    int t = threadIdx.x;
    int co = t % 160, nl = t / 160;
    int n = blockIdx.x*4 + nl;
    const float4* wr = (const float4*)(Wd + ((size_t)n*160 + co)*8);
    float4 w0 = wr[0], w1 = wr[1];
    __half* outp = g_uh16 + (size_t)n*160 + co;
    const float4* up = (const float4*)(g_u + (size_t)n*8);
    #pragma unroll 4
    for (int b = 0; b < BATCH; b++) {
        float4 ua = __ldg(up), ub = __ldg(up + 1);
        float a = w0.x*ua.x;
        a = fmaf(w0.y, ua.y, a); a = fmaf(w0.z, ua.z, a); a = fmaf(w0.w, ua.w, a);
        a = fmaf(w1.x, ub.x, a); a = fmaf(w1.y, ub.y, a);
        a = fmaf(w1.z, ub.z, a); a = fmaf(w1.w, ub.w, a);
        outp[(size_t)b*NCAP*160] = __float2half_rn(a);
        up += NCAP*8/4;
    }
}

// ---------------- routing from materialized fp16 u_hat ----------------
__device__ __forceinline__ void unpack8(const uint4& q, float* f) {
    const __half2* h = (const __half2*)&q;
    #pragma unroll
    for (int j = 0; j < 4; j++) {
        float2 v = __half22float2(h[j]);
        f[2*j] = v.x; f[2*j+1] = v.y;
    }
}

__global__ __launch_bounds__(512) void route16_kernel(int first, int last)
{
    int cp = blockIdx.x;
    int b  = blockIdx.y;
    int t  = threadIdx.x;
    __shared__ float sVc[32];
    __shared__ float sred[16][34];
    __shared__ float sfin[34];

    if (t < 32) sVc[t] = first ? 0.f : g_vc[(b*NCLS + 2*cp + (t >> 4))*OD + (t & 15)];
    __syncthreads();
    float Vc0[16], Vc1[16];
    #pragma unroll
    for (int o = 0; o < 16; o++) { Vc0[o] = sVc[o]; Vc1[o] = sVc[16+o]; }

    float se0 = 0.f, se1 = 0.f;
    float sv0[16], sv1[16];
    #pragma unroll
    for (int o = 0; o < 16; o++) { sv0[o] = 0.f; sv1[o] = 0.f; }

    #pragma unroll 1
    for (int j = 0; j < 9; j++) {
        int n = t + j*512;
        const uint4* up = (const uint4*)(g_uh16 + ((size_t)b*NCAP + n)*160 + cp*32);
        uint4 q0 = up[0], q1 = up[1], q2 = up[2], q3 = up[3];
        float uh0[16], uh1[16];
        unpack8(q0, uh0); unpack8(q1, uh0+8);
        unpack8(q2, uh1); unpack8(q3, uh1+8);
        float b0 = 0.f, b1 = 0.f;
        #pragma unroll
        for (int o = 0; o < 16; o++) {
            b0 = fmaf(uh0[o], Vc0[o], b0);
            b1 = fmaf(uh1[o], Vc1[o], b1);
        }
        float e0 = __expf(b0), e1 = __expf(b1);
        se0 += e0; se1 += e1;
        #pragma unroll
        for (int o = 0; o < 16; o++) {
            sv0[o] = fmaf(e0, uh0[o], sv0[o]);
            sv1[o] = fmaf(e1, uh1[o], sv1[o]);
        }
    }

    #pragma unroll
    for (int off = 16; off > 0; off >>= 1) {
        se0 += __shfl_down_sync(0xffffffffu, se0, off);
        se1 += __shfl_down_sync(0xffffffffu, se1, off);
        #pragma unroll
        for (int o = 0; o < 16; o++) {
            sv0[o] += __shfl_down_sync(0xffffffffu, sv0[o], off);
            sv1[o] += __shfl_down_sync(0xffffffffu, sv1[o], off);
        }
    }
    int wid = t >> 5, lane = t & 31;
    if (lane == 0) {
        sred[wid][0] = se0;
        sred[wid][17] = se1;
        #pragma unroll
        for (int o = 0; o < 16; o++) {
            sred[wid][1+o] = sv0[o];
            sred[wid][18+o] = sv1[o];
        }
    }
    __syncthreads();

    if (t < 34) {
        float tot = 0.f;
        #pragma unroll
        for (int w = 0; w < 16; w++) tot += sred[w][t];
        sfin[t] = tot;
    }
    __syncthreads();

    if (t < 32) {
        int c = t >> 4, o = t & 15;
        float se = sfin[c*17];
        float s = sfin[c*17 + 1 + o] / se;
        float s2 = s*s;
        #pragma unroll
        for (int off = 8; off > 0; off >>= 1)
            s2 += __shfl_xor_sync(0xffffffffu, s2, off, 16);
        float scale = (s2 / (1.f + s2)) / sqrtf(s2 + 1e-8f);
        float vv = scale * s;
        int cls = 2*cp + c;
        g_v[(b*NCLS + cls)*OD + o] = vv;
        if (!last) {
            if (first) g_vc[(b*NCLS + cls)*OD + o] = vv;
            else       g_vc[(b*NCLS + cls)*OD + o] += vv;
        }
    }
}

// ---------------- head ----------------
__global__ void head_kernel(float* __restrict__ out)
{
    int b = blockIdx.x;
    int t = threadIdx.x;
    __shared__ float len[NCLS];
    if (t < NCLS) {
        float s = 0.f;
        #pragma unroll
        for (int o = 0; o < OD; o++) {
            float x = g_v[(b*NCLS + t)*OD + o];
            s = fmaf(x, x, s);
        }
        len[t] = sqrtf(s);
    }
    __syncthreads();
    if (t == 0) {
        int best = 0; float bv = len[0];
        #pragma unroll
        for (int c = 1; c < NCLS; c++)
            if (len[c] > bv) { bv = len[c]; best = c; }
        g_cls[b] = best;
    }
    __syncthreads();
    int best = g_cls[b];
    if (t < NCLS) {
        out[OUT_OHE_OFF + b*NCLS + t] = (t == best) ? 1.0f : 0.0f;
        out[OUT_LEN_OFF + b*NCLS + t] = len[t];
    }
}

// ---------------- decoder ----------------
__global__ void dec1_kernel(const float* __restrict__ w1, const float* __restrict__ b1)
{
    int idx = blockIdx.x*256 + threadIdx.x;
    if (idx >= BATCH*512) return;
    int j = idx % 512, b = idx / 512;
    int cls = g_cls[b];
    const float* v = &g_v[(b*NCLS + cls)*OD];
    float a = b1[j];
    #pragma unroll
    for (int d = 0; d < OD; d++)
        a = fmaf(v[d], w1[(size_t)(cls*OD + d)*512 + j], a);
    g_h1[idx] = fmaxf(a, 0.f);
}

__global__ void dec2_kernel(const float* __restrict__ w2, const float* __restrict__ b2)
{
    int idx = blockIdx.x*256 + threadIdx.x;
    if (idx >= BATCH*1024) return;
    int j = idx % 1024, b = idx / 1024;
    const float* h = &g_h1[b*512];
    float a = b2[j];
    #pragma unroll 4
    for (int k = 0; k < 512; k++)
        a = fmaf(h[k], w2[(size_t)k*1024 + j], a);
    g_h2[idx] = fmaxf(a, 0.f);
}

__global__ void dec3_kernel(const float* __restrict__ w3, const float* __restrict__ b3,
                            float* __restrict__ out)
{
    int idx = blockIdx.x*256 + threadIdx.x;
    if (idx >= BATCH*784) return;
    int p = idx % 784, b = idx / 784;
    const float* h = &g_h2[b*1024];
    float a = b3[p];
    #pragma unroll 4
    for (int k = 0; k < 1024; k++)
        a = fmaf(h[k], w3[(size_t)k*784 + p], a);
    out[OUT_REC_OFF + idx] = 1.f / (1.f + expf(-a));
}

// ---------------- launch ----------------
extern "C" void kernel_launch(void* const* d_in, const int* in_sizes, int n_in,
                              void* d_out, int out_size)
{
    const float* imgs    = (const float*)d_in[0];
    const float* conv1_w = (const float*)d_in[1];
    const float* conv1_b = (const float*)d_in[2];
    const float* conv2_w = (const float*)d_in[3];
    const float* conv2_b = (const float*)d_in[4];
    const float* W_digit = (const float*)d_in[5];
    const float* dec_w1  = (const float*)d_in[6];
    const float* dec_b1  = (const float*)d_in[7];
    const float* dec_w2  = (const float*)d_in[8];
    const float* dec_b2  = (const float*)d_in[9];
    const float* dec_w3  = (const float*)d_in[10];
    const float* dec_b3  = (const float*)d_in[11];
    float* out = (float*)d_out;

    cudaFuncSetAttribute(conv2_tc_kernel,
                         cudaFuncAttributeMaxDynamicSharedMemorySize, CONV2_SMEM);
    cudaFuncSetAttribute(wsplit_kernel,
                         cudaFuncAttributeMaxDynamicSharedMemorySize, 65536);

    wsplit_kernel<<<NBLK, 256, 65536>>>(conv2_w);
    conv1_kernel<<<dim3(C1, BATCH), 256>>>(imgs, conv1_w, conv1_b);
    xpose_kernel<<<BATCH, 512>>>();
    conv2_tc_kernel<<<MTILES, 512, CONV2_SMEM>>>(conv2_b);
    uhat16_kernel<<<NCAP/4, 640>>>(W_digit);
    for (int it = 0; it < 3; it++)
        route16_kernel<<<dim3(5, BATCH), 512>>>(it == 0 ? 1 : 0, it == 2 ? 1 : 0);
    head_kernel<<<BATCH, 32>>>(out);
    dec1_kernel<<<(BATCH*512 + 255)/256, 256>>>(dec_w1, dec_b1);
    dec2_kernel<<<(BATCH*1024 + 255)/256, 256>>>(dec_w2, dec_b2);
    dec3_kernel<<<(BATCH*784 + 255)/256, 256>>>(dec_w3, dec_b3, out);
    (void)in_sizes; (void)n_in; (void)out_size;
}

// round 14
// speedup vs baseline: 4.5780x; 1.2640x over previous
#include <cuda_runtime.h>
#include <cuda_bf16.h>
#include <cuda_fp16.h>
#include <math.h>
#include <stdint.h>

// ---------------- problem constants ----------------
#define BATCH 128
#define C1 256
#define C2 256
#define NMAP 32
#define NPRIM 144
#define NCAP (NMAP*NPRIM)   // 4608
#define NCLS 10
#define OD 16
#define ID 8

#define OUT_OHE_OFF 0
#define OUT_REC_OFF (BATCH*NCLS)
#define OUT_LEN_OFF (BATCH*NCLS + BATCH*784)

// conv2 GEMM geometry (K reordered: k' = (ky*9+kx)*256 + ic)
#define KTOT 20736
#define KC   64
#define NBLK 324
#define MTILES 144

// ---------------- device scratch ----------------
// X packed: [b][px][seg0..3][hi 64 bf16 | lo 64 bf16]  (256B per (px,seg))
__device__ __nv_bfloat16 g_x[(size_t)BATCH*400*4*128];
// W pre-swizzled per 64KB chunk blocks (smem image, both planes)
__device__ __nv_bfloat16 g_wsw[(size_t)NBLK*65536/2];
__device__ float g_u[(size_t)BATCH*NCAP*ID];
// u_hat fp16, layout [b][cp(5)][n(4608)][32]
__device__ __half g_uh16[(size_t)BATCH*5*NCAP*32];
__device__ float g_v[BATCH*NCLS*OD];
__device__ float g_vc[BATCH*NCLS*OD];
__device__ int   g_cls[BATCH];
__device__ float g_h1[BATCH*512];
__device__ float g_h2[BATCH*1024];

// ---------------- small PTX helpers ----------------
__device__ __forceinline__ uint32_t smem_u32(const void* p) {
    uint32_t a;
    asm("{ .reg .u64 t; cvta.to.shared.u64 t, %1; cvt.u32.u64 %0, t; }"
        : "=r"(a) : "l"(p));
    return a;
}
__device__ __forceinline__ void ldsm4(uint32_t* r, uint32_t a) {
    asm volatile("ldmatrix.sync.aligned.m8n8.x4.shared.b16 {%0,%1,%2,%3}, [%4];"
        : "=r"(r[0]), "=r"(r[1]), "=r"(r[2]), "=r"(r[3]) : "r"(a));
}
__device__ __forceinline__ void ldsm4t(uint32_t* r, uint32_t a) {
    asm volatile("ldmatrix.sync.aligned.m8n8.x4.trans.shared.b16 {%0,%1,%2,%3}, [%4];"
        : "=r"(r[0]), "=r"(r[1]), "=r"(r[2]), "=r"(r[3]) : "r"(a));
}
__device__ __forceinline__ void mma_bf16(float* c, const uint32_t* a, const uint32_t* b) {
    asm volatile("mma.sync.aligned.m16n8k16.row.col.f32.bf16.bf16.f32 "
        "{%0,%1,%2,%3}, {%4,%5,%6,%7}, {%8,%9}, {%0,%1,%2,%3};"
        : "+f"(c[0]), "+f"(c[1]), "+f"(c[2]), "+f"(c[3])
        : "r"(a[0]), "r"(a[1]), "r"(a[2]), "r"(a[3]), "r"(b[0]), "r"(b[1]));
}
__device__ __forceinline__ void mbar_init(uint32_t mbar, uint32_t cnt) {
    asm volatile("mbarrier.init.shared.b64 [%0], %1;" :: "r"(mbar), "r"(cnt) : "memory");
}
__device__ __forceinline__ void mbar_expect(uint32_t mbar, uint32_t bytes) {
    asm volatile("mbarrier.arrive.expect_tx.shared.b64 _, [%0], %1;"
                 :: "r"(mbar), "r"(bytes) : "memory");
}
__device__ __forceinline__ void bulkcp(uint32_t dst, const void* src, uint32_t size,
                                       uint32_t mbar) {
    asm volatile(
        "cp.async.bulk.shared::cluster.global.mbarrier::complete_tx::bytes [%0], [%1], %2, [%3];"
        :: "r"(dst), "l"(src), "r"(size), "r"(mbar) : "memory");
}
__device__ __forceinline__ void mbar_wait(uint32_t mbar, uint32_t parity) {
    uint32_t done;
    asm volatile("{\n\t.reg .pred p;\n\t"
        "mbarrier.try_wait.parity.acquire.cta.shared::cta.b64 p, [%1], %2;\n\t"
        "selp.b32 %0, 1, 0, p;\n\t}" : "=r"(done) : "r"(mbar), "r"(parity) : "memory");
    while (!done) {
        asm volatile("{\n\t.reg .pred p;\n\t"
            "mbarrier.try_wait.parity.acquire.cta.shared::cta.b64 p, [%1], %2, 0x989680;\n\t"
            "selp.b32 %0, 1, 0, p;\n\t}" : "=r"(done) : "r"(mbar), "r"(parity) : "memory");
    }
}
__device__ __forceinline__ void fence_async_smem() {
    asm volatile("fence.proxy.async.shared::cta;" ::: "memory");
}

// smem layout per buffer: X rows (272B stride, 128 rows) then W (64KB swizzled image)
#define OFF_X  0u
#define OFF_W  34816u
#define BUFB   100352u
#define CONV2_SMEM (1024u + 2u*BUFB)   // 201728

// ---------------- fused conv1 + relu + bf16 split + pack into g_x ----------------
// grid (8 octiles, BATCH), 640 threads: thread = (ocl 0..31, oy 0..19)
#define CONV1_SMEM (812*4 + 2592*4 + 13200*4)   // 66416
__global__ __launch_bounds__(640) void conv1_kernel(
    const float* __restrict__ img, const float* __restrict__ w,
    const float* __restrict__ bias)
{
    extern __shared__ char cs[];
    float* si = (float*)cs;                       // [28][29]
    float* sw = si + 812;                         // [32][81]
    uint32_t* sout = (uint32_t*)(sw + 2592);      // [400][33]

    int octile = blockIdx.x, b = blockIdx.y;
    int t = threadIdx.x;

    for (int i = t; i < 784; i += 640) {
        int r = i / 28, c = i - r*28;
        si[r*29 + c] = img[b*784 + i];
    }
    for (int i = t; i < 32*81; i += 640)
        sw[i] = w[(octile*32 + i/81)*81 + (i % 81)];
    __syncthreads();

    int ocl = t / 20, oy = t % 20;
    float acc[20];
    {
        float bs = bias[octile*32 + ocl];
        #pragma unroll
        for (int ox = 0; ox < 20; ox++) acc[ox] = bs;
    }
    const float* swr = sw + ocl*81;
    #pragma unroll 1
    for (int ky = 0; ky < 9; ky++) {
        const float* row = si + (oy + ky)*29;
        float rv[28];
        #pragma unroll
        for (int i = 0; i < 28; i++) rv[i] = row[i];
        #pragma unroll
        for (int kx = 0; kx < 9; kx++) {
            float wv = swr[ky*9 + kx];
            #pragma unroll
            for (int ox = 0; ox < 20; ox++)
                acc[ox] = fmaf(wv, rv[ox + kx], acc[ox]);
        }
    }
    #pragma unroll
    for (int ox = 0; ox < 20; ox++) {
        float v = fmaxf(acc[ox], 0.f);
        __nv_bfloat16 h = __float2bfloat16(v);
        __nv_bfloat16 l = __float2bfloat16(v - __bfloat162float(h));
        uint32_t pk = (uint32_t)__bfloat16_as_ushort(h)
                    | ((uint32_t)__bfloat16_as_ushort(l) << 16);
        sout[(oy*20 + ox)*33 + ocl] = pk;
    }
    __syncthreads();

    int seg = octile >> 1;
    int iclb = (octile & 1) * 32;
    for (int i = t; i < 400*32; i += 640) {
        int px = i >> 5, c = i & 31;
        uint32_t pk = sout[px*33 + c];
        size_t base = (((size_t)b*400 + px)*4 + seg) * 128;
        g_x[base + iclb + c]      = __ushort_as_bfloat16((unsigned short)(pk & 0xFFFFu));
        g_x[base + 64 + iclb + c] = __ushort_as_bfloat16((unsigned short)(pk >> 16));
    }
}

// ---------------- W split: block per 64KB chunk, smem-staged coalesced output ----------------
__global__ __launch_bounds__(256) void wsplit_kernel(const float* __restrict__ w2)
{
    extern __shared__ char img[];      // 65536 bytes
    int kb = blockIdx.x;
    int r   = kb >> 2;
    int ic0 = (kb & 3) * 64;
    int t = threadIdx.x;               // = oc
    const float* src = w2 + (size_t)t*KTOT + (size_t)ic0*81 + r;
    #pragma unroll 4
    for (int icl = 0; icl < 64; icl++) {
        float v = src[icl*81];
        __nv_bfloat16 h = __float2bfloat16(v);
        __nv_bfloat16 l = __float2bfloat16(v - __bfloat162float(h));
        uint32_t byte = (uint32_t)(icl*512 + ((t*2) ^ ((icl & 7) << 4)));
        *(__nv_bfloat16*)(img + byte)         = h;
        *(__nv_bfloat16*)(img + byte + 32768) = l;
    }
    __syncthreads();
    const uint4* s4 = (const uint4*)img;
    uint4* d4 = (uint4*)((char*)g_wsw + (size_t)kb*65536);
    #pragma unroll
    for (int i = 0; i < 16; i++)
        d4[t + i*256] = s4[t + i*256];
}

// ---------------- conv2 tensor-core kernel (bulk staging + fused squash epilogue) ----------------
__global__ void __launch_bounds__(512, 1) conv2_tc_kernel(const float* __restrict__ b2)
{
    extern __shared__ char smem[];
    uint32_t sbase = smem_u32(smem);
    int t = threadIdx.x;
    int warp = t >> 5, lane = t & 31;
    int tile = blockIdx.x;

    int warp_m = warp >> 2;
    int warp_n = warp & 3;

    int trow = (t < 128) ? t : 0;
    int grow = tile*128 + trow;
    int bimg = grow / NPRIM;
    int posl = grow - bimg*NPRIM;
    int oy = posl / 12, ox = posl - (posl/12)*12;
    int xb400 = bimg*400;

    uint32_t mbar0 = sbase, mbar1 = sbase + 8;

    if (t == 0) { mbar_init(mbar0, 129); mbar_init(mbar1, 129); fence_async_smem(); }
    __syncthreads();

    float acc[2][8][4];
    #pragma unroll
    for (int mt = 0; mt < 2; mt++)
        #pragma unroll
        for (int nt = 0; nt < 8; nt++)
            #pragma unroll
            for (int e = 0; e < 4; e++) acc[mt][nt][e] = 0.f;

    auto stage = [&](int kn, uint32_t buf, uint32_t mbar) {
        if (t < 128) {
            int r = kn >> 2, seg = kn & 3;
            int ky = r / 9, kx = r - ky*9;
            const char* src = (const char*)g_x
                + ((((size_t)(xb400 + (oy+ky)*20 + ox + kx))*4 + seg) << 8);
            mbar_expect(mbar, 256);
            bulkcp(buf + OFF_X + (uint32_t)t*272u, src, 256, mbar);
        } else if (t == 128) {
            mbar_expect(mbar, 65536);
            bulkcp(buf + OFF_W, (const char*)g_wsw + (size_t)kn*65536, 65536, mbar);
        }
    };

    uint32_t buf0 = sbase + 1024u, buf1 = sbase + 1024u + BUFB;
    stage(0, buf0, mbar0);

    int ph0 = 0, ph1 = 0;
    for (int kb = 0; kb < NBLK; kb++) {
        int cur = kb & 1;
        uint32_t curbuf = cur ? buf1 : buf0;
        if (kb + 1 < NBLK)
            stage(kb + 1, cur ? buf0 : buf1, cur ? mbar0 : mbar1);

        if (cur) { mbar_wait(mbar1, ph1); }
        else     { mbar_wait(mbar0, ph0); }

        #pragma unroll
        for (int kk = 0; kk < 4; kk++) {
            uint32_t bh[8][2], bl[8][2];
            #pragma unroll
            for (int np = 0; np < 4; np++) {
                int j = lane >> 3, rw = lane & 7;
                int krow = kk*16 + (j & 1)*8 + rw;
                int ncol = warp_n*64 + np*16 + (j >> 1)*8;
                uint32_t byte = (uint32_t)(krow*512 + ((ncol*2) ^ ((krow & 7) << 4)));
                uint32_t r[4];
                ldsm4t(r, curbuf + OFF_W + byte);
                bh[2*np][0] = r[0]; bh[2*np][1] = r[1];
                bh[2*np+1][0] = r[2]; bh[2*np+1][1] = r[3];
                ldsm4t(r, curbuf + OFF_W + 32768u + byte);
                bl[2*np][0] = r[0]; bl[2*np][1] = r[1];
                bl[2*np+1][0] = r[2]; bl[2*np+1][1] = r[3];
            }
            #pragma unroll
            for (int mt = 0; mt < 2; mt++) {
                int rowl = warp_m*32 + mt*16 + (lane & 15);
                uint32_t abase = curbuf + OFF_X + (uint32_t)rowl*272u
                               + (uint32_t)((kk*16 + (lane >> 4)*8)*2);
                uint32_t ah[4], al[4];
                ldsm4(ah, abase);
                ldsm4(al, abase + 128u);
                #pragma unroll
                for (int nt = 0; nt < 8; nt++) {
                    mma_bf16(acc[mt][nt], ah, bh[nt]);
                    mma_bf16(acc[mt][nt], ah, bl[nt]);
                    mma_bf16(acc[mt][nt], al, bh[nt]);
                }
            }
        }
        if (cur) ph1 ^= 1; else ph0 ^= 1;
        __syncthreads();
    }

    // ---- fused epilogue: stage D in smem, squash, write g_u directly ----
    float* sD = (float*)(smem + 1024);     // [128 pos][stride 260]
    #pragma unroll
    for (int mt = 0; mt < 2; mt++) {
        int pr = warp_m*32 + mt*16 + (lane >> 2);
        #pragma unroll
        for (int half = 0; half < 2; half++) {
            int p2 = pr + half*8;
            #pragma unroll
            for (int nt = 0; nt < 8; nt++) {
                int oc = warp_n*64 + nt*8 + (lane & 3)*2;
                sD[p2*260 + oc]     = acc[mt][nt][half*2 + 0] + __ldg(&b2[oc]);
                sD[p2*260 + oc + 1] = acc[mt][nt][half*2 + 1] + __ldg(&b2[oc+1]);
            }
        }
    }
    __syncthreads();

    #pragma unroll 1
    for (int iter = 0; iter < 8; iter++) {
        int q = iter*512 + t;
        int pos = q & 127;
        int m   = q >> 7;
        int gq = tile*128 + pos;
        int b  = gq / NPRIM;
        int pl = gq - b*NPRIM;
        float x[8]; float s2 = 0.f;
        #pragma unroll
        for (int d = 0; d < 8; d++) {
            x[d] = sD[pos*260 + m + d*32];
            s2 = fmaf(x[d], x[d], s2);
        }
        float scale = (s2 / (1.f + s2)) / sqrtf(s2 + 1e-8f);
        float4* up = (float4*)(g_u + ((size_t)b*NCAP + m*NPRIM + pl)*8);
        up[0] = make_float4(scale*x[0], scale*x[1], scale*x[2], scale*x[3]);
        up[1] = make_float4(scale*x[4], scale*x[5], scale*x[6], scale*x[7]);
    }
}

// ---------------- u_hat materialization (fp16, layout [b][cp][n][32]) ----------------
__global__ __launch_bounds__(640) void uhat16_kernel(const float* __restrict__ Wd)
{
    int t = threadIdx.x;
    int co = t % 160, nl = t / 160;
    int n = blockIdx.x*4 + nl;
    int c = co >> 4, o = co & 15;
    int cp = c >> 1, cl = c & 1;
    const float4* wr = (const float4*)(Wd + ((size_t)n*160 + co)*8);
    float4 w0 = wr[0], w1 = wr[1];
    __half* outp = g_uh16 + (((size_t)cp*NCAP + n)*32 + cl*16 + o);
    const float4* up = (const float4*)(g_u + (size_t)n*8);
    const size_t bstride = (size_t)5*NCAP*32;
    #pragma unroll 4
    for (int b = 0; b < BATCH; b++) {
        float4 ua = __ldg(up), ub = __ldg(up + 1);
        float a = w0.x*ua.x;
        a = fmaf(w0.y, ua.y, a); a = fmaf(w0.z, ua.z, a); a = fmaf(w0.w, ua.w, a);
        a = fmaf(w1.x, ub.x, a); a = fmaf(w1.y, ub.y, a);
        a = fmaf(w1.z, ub.z, a); a = fmaf(w1.w, ub.w, a);
        outp[(size_t)b*bstride] = __float2half_rn(a);
        up += NCAP*8/4;
    }
}

// ---------------- routing from materialized fp16 u_hat ----------------
__device__ __forceinline__ void unpack8(const uint4& q, float* f) {
    const __half2* h = (const __half2*)&q;
    #pragma unroll
    for (int j = 0; j < 4; j++) {
        float2 v = __half22float2(h[j]);
        f[2*j] = v.x; f[2*j+1] = v.y;
    }
}

__global__ __launch_bounds__(512) void route16_kernel(int first, int last)
{
    int cp = blockIdx.x;
    int b  = blockIdx.y;
    int t  = threadIdx.x;
    __shared__ float sVc[32];
    __shared__ float sred[16][34];
    __shared__ float sfin[34];

    if (t < 32) sVc[t] = first ? 0.f : g_vc[(b*NCLS + 2*cp + (t >> 4))*OD + (t & 15)];
    __syncthreads();
    float Vc0[16], Vc1[16];
    #pragma unroll
    for (int o = 0; o < 16; o++) { Vc0[o] = sVc[o]; Vc1[o] = sVc[16+o]; }

    float se0 = 0.f, se1 = 0.f;
    float sv0[16], sv1[16];
    #pragma unroll
    for (int o = 0; o < 16; o++) { sv0[o] = 0.f; sv1[o] = 0.f; }

    const __half* ubase = g_uh16 + ((size_t)b*5 + cp)*NCAP*32;

    #pragma unroll 1
    for (int j = 0; j < 9; j++) {
        int n = t + j*512;
        const uint4* up = (const uint4*)(ubase + (size_t)n*32);
        uint4 q0 = up[0], q1 = up[1], q2 = up[2], q3 = up[3];
        float uh0[16], uh1[16];
        unpack8(q0, uh0); unpack8(q1, uh0+8);
        unpack8(q2, uh1); unpack8(q3, uh1+8);
        float b0 = 0.f, b1 = 0.f;
        #pragma unroll
        for (int o = 0; o < 16; o++) {
            b0 = fmaf(uh0[o], Vc0[o], b0);
            b1 = fmaf(uh1[o], Vc1[o], b1);
        }
        float e0 = __expf(b0), e1 = __expf(b1);
        se0 += e0; se1 += e1;
        #pragma unroll
        for (int o = 0; o < 16; o++) {
            sv0[o] = fmaf(e0, uh0[o], sv0[o]);
            sv1[o] = fmaf(e1, uh1[o], sv1[o]);
        }
    }

    #pragma unroll
    for (int off = 16; off > 0; off >>= 1) {
        se0 += __shfl_down_sync(0xffffffffu, se0, off);
        se1 += __shfl_down_sync(0xffffffffu, se1, off);
        #pragma unroll
        for (int o = 0; o < 16; o++) {
            sv0[o] += __shfl_down_sync(0xffffffffu, sv0[o], off);
            sv1[o] += __shfl_down_sync(0xffffffffu, sv1[o], off);
        }
    }
    int wid = t >> 5, lane = t & 31;
    if (lane == 0) {
        sred[wid][0] = se0;
        sred[wid][17] = se1;
        #pragma unroll
        for (int o = 0; o < 16; o++) {
            sred[wid][1+o] = sv0[o];
            sred[wid][18+o] = sv1[o];
        }
    }
    __syncthreads();

    if (t < 34) {
        float tot = 0.f;
        #pragma unroll
        for (int w = 0; w < 16; w++) tot += sred[w][t];
        sfin[t] = tot;
    }
    __syncthreads();

    if (t < 32) {
        int c = t >> 4, o = t & 15;
        float se = sfin[c*17];
        float s = sfin[c*17 + 1 + o] / se;
        float s2 = s*s;
        #pragma unroll
        for (int off = 8; off > 0; off >>= 1)
            s2 += __shfl_xor_sync(0xffffffffu, s2, off, 16);
        float scale = (s2 / (1.f + s2)) / sqrtf(s2 + 1e-8f);
        float vv = scale * s;
        int cls = 2*cp + c;
        g_v[(b*NCLS + cls)*OD + o] = vv;
        if (!last) {
            if (first) g_vc[(b*NCLS + cls)*OD + o] = vv;
            else       g_vc[(b*NCLS + cls)*OD + o] += vv;
        }
    }
}

// ---------------- head ----------------
__global__ void head_kernel(float* __restrict__ out)
{
    int b = blockIdx.x;
    int t = threadIdx.x;
    __shared__ float len[NCLS];
    if (t < NCLS) {
        float s = 0.f;
        #pragma unroll
        for (int o = 0; o < OD; o++) {
            float x = g_v[(b*NCLS + t)*OD + o];
            s = fmaf(x, x, s);
        }
        len[t] = sqrtf(s);
    }
    __syncthreads();
    if (t == 0) {
        int best = 0; float bv = len[0];
        #pragma unroll
        for (int c = 1; c < NCLS; c++)
            if (len[c] > bv) { bv = len[c]; best = c; }
        g_cls[b] = best;
    }
    __syncthreads();
    int best = g_cls[b];
    if (t < NCLS) {
        out[OUT_OHE_OFF + b*NCLS + t] = (t == best) ? 1.0f : 0.0f;
        out[OUT_LEN_OFF + b*NCLS + t] = len[t];
    }
}

// ---------------- decoder ----------------
__global__ void dec1_kernel(const float* __restrict__ w1, const float* __restrict__ b1)
{
    int idx = blockIdx.x*256 + threadIdx.x;
    if (idx >= BATCH*512) return;
    int j = idx % 512, b = idx / 512;
    int cls = g_cls[b];
    const float* v = &g_v[(b*NCLS + cls)*OD];
    float a = b1[j];
    #pragma unroll
    for (int d = 0; d < OD; d++)
        a = fmaf(v[d], w1[(size_t)(cls*OD + d)*512 + j], a);
    g_h1[idx] = fmaxf(a, 0.f);
}

__global__ void dec2_kernel(const float* __restrict__ w2, const float* __restrict__ b2)
{
    int idx = blockIdx.x*256 + threadIdx.x;
    if (idx >= BATCH*1024) return;
    int j = idx % 1024, b = idx / 1024;
    const float* h = &g_h1[b*512];
    float a = b2[j];
    #pragma unroll 4
    for (int k = 0; k < 512; k++)
        a = fmaf(h[k], w2[(size_t)k*1024 + j], a);
    g_h2[idx] = fmaxf(a, 0.f);
}

__global__ void dec3_kernel(const float* __restrict__ w3, const float* __restrict__ b3,
                            float* __restrict__ out)
{
    int idx = blockIdx.x*256 + threadIdx.x;
    if (idx >= BATCH*784) return;
    int p = idx % 784, b = idx / 784;
    const float* h = &g_h2[b*1024];
    float a = b3[p];
    #pragma unroll 4
    for (int k = 0; k < 1024; k++)
        a = fmaf(h[k], w3[(size_t)k*784 + p], a);
    out[OUT_REC_OFF + idx] = 1.f / (1.f + expf(-a));
}

// ---------------- launch ----------------
extern "C" void kernel_launch(void* const* d_in, const int* in_sizes, int n_in,
                              void* d_out, int out_size)
{
    const float* imgs    = (const float*)d_in[0];
    const float* conv1_w = (const float*)d_in[1];
    const float* conv1_b = (const float*)d_in[2];
    const float* conv2_w = (const float*)d_in[3];
    const float* conv2_b = (const float*)d_in[4];
    const float* W_digit = (const float*)d_in[5];
    const float* dec_w1  = (const float*)d_in[6];
    const float* dec_b1  = (const float*)d_in[7];
    const float* dec_w2  = (const float*)d_in[8];
    const float* dec_b2  = (const float*)d_in[9];
    const float* dec_w3  = (const float*)d_in[10];
    const float* dec_b3  = (const float*)d_in[11];
    float* out = (float*)d_out;

    cudaFuncSetAttribute(conv2_tc_kernel,
                         cudaFuncAttributeMaxDynamicSharedMemorySize, CONV2_SMEM);
    cudaFuncSetAttribute(wsplit_kernel,
                         cudaFuncAttributeMaxDynamicSharedMemorySize, 65536);
    cudaFuncSetAttribute(conv1_kernel,
                         cudaFuncAttributeMaxDynamicSharedMemorySize, CONV1_SMEM);

    wsplit_kernel<<<NBLK, 256, 65536>>>(conv2_w);
    conv1_kernel<<<dim3(8, BATCH), 640, CONV1_SMEM>>>(imgs, conv1_w, conv1_b);
    conv2_tc_kernel<<<MTILES, 512, CONV2_SMEM>>>(conv2_b);
    uhat16_kernel<<<NCAP/4, 640>>>(W_digit);
    for (int it = 0; it < 3; it++)
        route16_kernel<<<dim3(5, BATCH), 512>>>(it == 0 ? 1 : 0, it == 2 ? 1 : 0);
    head_kernel<<<BATCH, 32>>>(out);
    dec1_kernel<<<(BATCH*512 + 255)/256, 256>>>(dec_w1, dec_b1);
    dec2_kernel<<<(BATCH*1024 + 255)/256, 256>>>(dec_w2, dec_b2);
    dec3_kernel<<<(BATCH*784 + 255)/256, 256>>>(dec_w3, dec_b3, out);
    (void)in_sizes; (void)n_in; (void)out_size;
}